// round 4
// baseline (speedup 1.0000x reference)
#include <cuda_runtime.h>
#include <math.h>

#define C_EMBD 768
#define NH     12
#define HD     64
#define T_SEQ  4096
#define BATCH  2
#define M_ROWS (BATCH * T_SEQ)   // 8192

__device__ float g_qkv[(size_t)BATCH * T_SEQ * 3 * C_EMBD]; // [B,T,3C]
__device__ float g_y  [(size_t)BATCH * T_SEQ * C_EMBD];     // [B,T,C]

__device__ __forceinline__ unsigned f2tf32(float x) {
    unsigned r;
    asm("cvt.rna.tf32.f32 %0, %1;" : "=r"(r) : "f"(x));
    return r;
}
__device__ __forceinline__ float ex2(float x) {
    float r;
    asm("ex2.approx.f32 %0, %1;" : "=f"(r) : "f"(x));
    return r;
}
__device__ __forceinline__ void mma16n8k8(float* c, const unsigned* a, const unsigned* b) {
    asm volatile(
        "mma.sync.aligned.m16n8k8.row.col.f32.tf32.tf32.f32 "
        "{%0,%1,%2,%3}, {%4,%5,%6,%7}, {%8,%9}, {%0,%1,%2,%3};\n"
        : "+f"(c[0]), "+f"(c[1]), "+f"(c[2]), "+f"(c[3])
        : "r"(a[0]), "r"(a[1]), "r"(a[2]), "r"(a[3]), "r"(b[0]), "r"(b[1]));
}
__device__ __forceinline__ unsigned smem_u32(const void* p) {
    return (unsigned)__cvta_generic_to_shared(p);
}
__device__ __forceinline__ void cp_async16(unsigned saddr, const void* g) {
    asm volatile("cp.async.cg.shared.global [%0], [%1], 16;\n" :: "r"(saddr), "l"(g));
}
#define CP_COMMIT() asm volatile("cp.async.commit_group;\n")
#define CP_WAIT(n)  asm volatile("cp.async.wait_group %0;\n" :: "n"(n))

// 16-element group permute: output float4 at pos 4c = cols {c, c+4, c+8, c+12}
// (self-inverse). Enables LDS.128 giving fragments for two consecutive k-steps.

// ---------------------------------------------------------------------------
// TF32 GEMM + bias. 128x128 tile, BK=32, 256 thr = 8 warps (4M x 2N).
// A cp.async'd into permuted-layout buffer (stride 48), cvt+permuted in place.
// B cp.async'd raw (stride 132), transposed+cvt to Bt[n][k] (stride 48).
// Inner loop: LDS.128-only fragments, no cvt.
// ---------------------------------------------------------------------------
#define AP_STR 48
#define BR_STR 132
#define BT_STR 48
#define GEMM_SMEM ((2 * 128 * AP_STR + 2 * 32 * BR_STR + 128 * BT_STR) * 4)

__global__ __launch_bounds__(256, 2) void sgemm_tf32(
    const float* __restrict__ A, const float* __restrict__ B,
    const float* __restrict__ bias, float* __restrict__ Cm,
    int M, int N, int K)
{
    extern __shared__ float sm[];
    float* Ap   = sm;                          // 2 x [128][AP_STR]
    float* Braw = Ap + 2 * 128 * AP_STR;       // 2 x [32][BR_STR]
    float* Bt   = Braw + 2 * 32 * BR_STR;      // [128][BT_STR]

    const int tid  = threadIdx.x;
    const int warp = tid >> 5, lane = tid & 31;
    const int wm = warp & 3, wn = warp >> 2;
    const int g = lane >> 2, c = lane & 3;

    const int by = blockIdx.y, bx = blockIdx.x;
    const float* Ab = A + (size_t)by * 128 * K;
    const float* Bb = B + (size_t)bx * 128;

    float acc[2][8][4];
    #pragma unroll
    for (int mt = 0; mt < 2; mt++)
        #pragma unroll
        for (int nt = 0; nt < 8; nt++)
            #pragma unroll
            for (int r = 0; r < 4; r++) acc[mt][nt][r] = 0.f;

    const int am = tid >> 3, ak = (tid & 7) * 4;   // A loader
    const int bk = tid >> 5, bn = (tid & 31) * 4;  // B loader

    #define LOAD_STAGE(s, k0)                                                        \
        {                                                                            \
            _Pragma("unroll")                                                        \
            for (int i = 0; i < 4; i++) {                                            \
                cp_async16(smem_u32(&Ap[(s) * 128 * AP_STR + (am + i * 32) * AP_STR + ak]), \
                           &Ab[(size_t)(am + i * 32) * K + (k0) + ak]);              \
                cp_async16(smem_u32(&Braw[(s) * 32 * BR_STR + (bk + i * 8) * BR_STR + bn]), \
                           &Bb[(size_t)((k0) + bk + i * 8) * N + bn]);               \
            }                                                                        \
        }

    LOAD_STAGE(0, 0);
    CP_COMMIT();

    const int NK = K / 32;
    for (int kt = 0; kt < NK; kt++) {
        CP_WAIT(0);
        __syncthreads();

        // ---- cvt + permute A in place (thread owns one 16-col group) ----
        {
            float* base = &Ap[(kt & 1) * 128 * AP_STR + (tid >> 1) * AP_STR + (tid & 1) * 16];
            float f[16];
            #pragma unroll
            for (int j = 0; j < 4; j++) *(float4*)&f[4 * j] = *(float4*)&base[4 * j];
            #pragma unroll
            for (int cc = 0; cc < 4; cc++) {
                uint4 o = make_uint4(f2tf32(f[cc]), f2tf32(f[cc + 4]),
                                     f2tf32(f[cc + 8]), f2tf32(f[cc + 12]));
                *(uint4*)&base[4 * cc] = o;
            }
        }
        // ---- transpose + cvt B -> Bt[n][k] permuted ----
        {
            const float* braw = &Braw[(kt & 1) * 32 * BR_STR];
            #pragma unroll
            for (int it = 0; it < 4; it++) {
                int j = tid + it * 256;
                int ti = j & 7, n = j >> 3;
                int t_ = ti >> 2, i_ = ti & 3;
                unsigned o[4];
                #pragma unroll
                for (int jp = 0; jp < 4; jp++) {
                    int jt = (jp + t_) & 3;
                    o[jt] = f2tf32(braw[(16 * t_ + i_ + 4 * jt) * BR_STR + n]);
                }
                *(uint4*)&Bt[n * BT_STR + t_ * 16 + 4 * i_] =
                    make_uint4(o[0], o[1], o[2], o[3]);
            }
        }
        __syncthreads();

        if (kt + 1 < NK) { LOAD_STAGE((kt + 1) & 1, (kt + 1) * 32); }
        CP_COMMIT();

        // ---- compute: 2 ks-pairs x (4 A-LDS.128 + 8 B-LDS.128 + 32 MMA) ----
        const float* Asb = &Ap[(kt & 1) * 128 * AP_STR];
        #pragma unroll
        for (int tp = 0; tp < 2; tp++) {
            unsigned ae[2][4], ao[2][4];
            #pragma unroll
            for (int mt = 0; mt < 2; mt++) {
                int m0 = wm * 32 + mt * 16;
                uint4 f0 = *(uint4*)&Asb[(m0 + g    ) * AP_STR + tp * 16 + 4 * c];
                uint4 f1 = *(uint4*)&Asb[(m0 + g + 8) * AP_STR + tp * 16 + 4 * c];
                ae[mt][0] = f0.x; ae[mt][1] = f1.x; ae[mt][2] = f0.y; ae[mt][3] = f1.y;
                ao[mt][0] = f0.z; ao[mt][1] = f1.z; ao[mt][2] = f0.w; ao[mt][3] = f1.w;
            }
            #pragma unroll
            for (int nt = 0; nt < 8; nt++) {
                int n0 = wn * 64 + nt * 8;
                uint4 fb = *(uint4*)&Bt[(n0 + g) * BT_STR + tp * 16 + 4 * c];
                unsigned be[2] = {fb.x, fb.y}, bo[2] = {fb.z, fb.w};
                mma16n8k8(acc[0][nt], ae[0], be);
                mma16n8k8(acc[1][nt], ae[1], be);
                mma16n8k8(acc[0][nt], ao[0], bo);
                mma16n8k8(acc[1][nt], ao[1], bo);
            }
        }
    }

    #pragma unroll
    for (int mt = 0; mt < 2; mt++) {
        #pragma unroll
        for (int nt = 0; nt < 8; nt++) {
            int row0 = by * 128 + wm * 32 + mt * 16 + g;
            int col  = bx * 128 + wn * 64 + nt * 8 + 2 * c;
            float2 bv = *(const float2*)&bias[col];
            float2 o0 = make_float2(acc[mt][nt][0] + bv.x, acc[mt][nt][1] + bv.y);
            float2 o1 = make_float2(acc[mt][nt][2] + bv.x, acc[mt][nt][3] + bv.y);
            *(float2*)&Cm[(size_t)row0 * N + col]       = o0;
            *(float2*)&Cm[(size_t)(row0 + 8) * N + col] = o1;
        }
    }
}

// ---------------------------------------------------------------------------
// Flash attention, TF32. Br=128, Bc=64, 256 thr = 8 warps (16 rows each).
// K cp.async'd into permuted buffer (stride 80, double), cvt in place.
// V cp.async'd raw (stride 64), transposed+cvt to Vt[d][key] (stride 80).
// ---------------------------------------------------------------------------
#define KP_STR 80
#define VR_STR 64
#define VT_STR 80
#define PQ_STR 68
#define FA_SMEM ((2 * 64 * KP_STR + 64 * VR_STR + 64 * VT_STR + 128 * PQ_STR) * 4)

__global__ __launch_bounds__(256, 2) void flash_attn_tf32(
    const float* __restrict__ qkv, float* __restrict__ y)
{
    extern __shared__ float sm[];
    float* sKp = sm;                          // 2 x [64][KP_STR]
    float* sVr = sKp + 2 * 64 * KP_STR;       // [64][VR_STR]
    float* sVt = sVr + 64 * VR_STR;           // [64][VT_STR]
    float* sPQ = sVt + 64 * VT_STR;           // [128][PQ_STR]

    const int tid  = threadIdx.x;
    const int warp = tid >> 5, lane = tid & 31;
    const int g = lane >> 2, c = lane & 3;
    const int qb = blockIdx.x;
    const int bh = blockIdx.y;
    const int b = bh / NH, h = bh % NH;

    const size_t rowstr = 3 * C_EMBD;
    const float* qp = qkv + ((size_t)(b * T_SEQ + qb * 128)) * rowstr + h * HD;
    const float* kp = qkv + ((size_t)b * T_SEQ) * rowstr + C_EMBD + h * HD;
    const float* vp = qkv + ((size_t)b * T_SEQ) * rowstr + 2 * C_EMBD + h * HD;
    const float qscale = 0.125f * 1.4426950408889634f;

    // ---- stage Q, pull A-fragments (scaled tf32) ----
    #pragma unroll
    for (int i = 0; i < 8; i++) {
        int idx = tid + i * 256;
        int row = idx >> 4, d4 = (idx & 15) << 2;
        *(float4*)&sPQ[row * PQ_STR + d4] = *(const float4*)&qp[(size_t)row * rowstr + d4];
    }
    __syncthreads();
    const int r0 = 16 * warp + g;
    unsigned qa[8][4];
    #pragma unroll
    for (int ks = 0; ks < 8; ks++) {
        int kk = ks * 8;
        qa[ks][0] = f2tf32(sPQ[(r0    ) * PQ_STR + kk + c]     * qscale);
        qa[ks][1] = f2tf32(sPQ[(r0 + 8) * PQ_STR + kk + c]     * qscale);
        qa[ks][2] = f2tf32(sPQ[(r0    ) * PQ_STR + kk + c + 4] * qscale);
        qa[ks][3] = f2tf32(sPQ[(r0 + 8) * PQ_STR + kk + c + 4] * qscale);
    }

    const int lr = tid >> 4, ld4 = (tid & 15) << 2;
    #define LOAD_K(s, t0)                                                           \
        {                                                                           \
            _Pragma("unroll")                                                       \
            for (int i = 0; i < 4; i++)                                             \
                cp_async16(smem_u32(&sKp[(s) * 64 * KP_STR + (lr + i * 16) * KP_STR + ld4]), \
                           &kp[(size_t)((t0) + lr + i * 16) * rowstr + ld4]);       \
        }
    #define LOAD_V(t0)                                                              \
        {                                                                           \
            _Pragma("unroll")                                                       \
            for (int i = 0; i < 4; i++)                                             \
                cp_async16(smem_u32(&sVr[(lr + i * 16) * VR_STR + ld4]),            \
                           &vp[(size_t)((t0) + lr + i * 16) * rowstr + ld4]);       \
        }

    LOAD_K(0, 0);
    LOAD_V(0);
    CP_COMMIT();

    float m0r = -INFINITY, m1r = -INFINITY, l0 = 0.f, l1 = 0.f;
    float oc[8][4];
    #pragma unroll
    for (int dt = 0; dt < 8; dt++)
        #pragma unroll
        for (int r = 0; r < 4; r++) oc[dt][r] = 0.f;

    const int NT = T_SEQ / 64;
    for (int t = 0; t < NT; t++) {
        CP_WAIT(0);
        __syncthreads();

        // ---- cvt + permute K(t) in place ----
        {
            float* base = &sKp[(t & 1) * 64 * KP_STR + (tid >> 2) * KP_STR + (tid & 3) * 16];
            float f[16];
            #pragma unroll
            for (int j = 0; j < 4; j++) *(float4*)&f[4 * j] = *(float4*)&base[4 * j];
            #pragma unroll
            for (int cc = 0; cc < 4; cc++) {
                uint4 o = make_uint4(f2tf32(f[cc]), f2tf32(f[cc + 4]),
                                     f2tf32(f[cc + 8]), f2tf32(f[cc + 12]));
                *(uint4*)&base[4 * cc] = o;
            }
        }
        // ---- transpose + cvt V(t) -> Vt[d][key] permuted ----
        #pragma unroll
        for (int it = 0; it < 4; it++) {
            int j = tid + it * 256;
            int ti = j & 15, d = j >> 4;
            int t_ = ti >> 2, i_ = ti & 3;
            unsigned o[4];
            #pragma unroll
            for (int jp = 0; jp < 4; jp++) {
                int jt = (jp + t_) & 3;
                o[jt] = f2tf32(sVr[(16 * t_ + i_ + 4 * jt) * VR_STR + d]);
            }
            *(uint4*)&sVt[d * VT_STR + t_ * 16 + 4 * i_] =
                make_uint4(o[0], o[1], o[2], o[3]);
        }
        __syncthreads();

        if (t + 1 < NT) { LOAD_K((t + 1) & 1, (t + 1) * 64); LOAD_V((t + 1) * 64); }
        CP_COMMIT();

        const float* Kb = &sKp[(t & 1) * 64 * KP_STR];

        // ---- S = Q @ K^T : 4 ks-pairs ----
        float sc[8][4];
        #pragma unroll
        for (int nt = 0; nt < 8; nt++)
            #pragma unroll
            for (int r = 0; r < 4; r++) sc[nt][r] = 0.f;

        #pragma unroll
        for (int tp = 0; tp < 4; tp++) {
            #pragma unroll
            for (int nt = 0; nt < 8; nt++) {
                uint4 kf = *(uint4*)&Kb[(nt * 8 + g) * KP_STR + tp * 16 + 4 * c];
                unsigned be[2] = {kf.x, kf.y}, bo[2] = {kf.z, kf.w};
                mma16n8k8(sc[nt], qa[2 * tp],     be);
                mma16n8k8(sc[nt], qa[2 * tp + 1], bo);
            }
        }

        // ---- online softmax (base-2) ----
        float rm0 = -INFINITY, rm1 = -INFINITY;
        #pragma unroll
        for (int nt = 0; nt < 8; nt++) {
            rm0 = fmaxf(rm0, fmaxf(sc[nt][0], sc[nt][1]));
            rm1 = fmaxf(rm1, fmaxf(sc[nt][2], sc[nt][3]));
        }
        rm0 = fmaxf(rm0, __shfl_xor_sync(0xffffffffu, rm0, 1));
        rm0 = fmaxf(rm0, __shfl_xor_sync(0xffffffffu, rm0, 2));
        rm1 = fmaxf(rm1, __shfl_xor_sync(0xffffffffu, rm1, 1));
        rm1 = fmaxf(rm1, __shfl_xor_sync(0xffffffffu, rm1, 2));

        float mn0 = fmaxf(m0r, rm0), mn1 = fmaxf(m1r, rm1);
        float corr0 = ex2(m0r - mn0), corr1 = ex2(m1r - mn1);
        m0r = mn0; m1r = mn1;

        float s0 = 0.f, s1 = 0.f;
        #pragma unroll
        for (int nt = 0; nt < 8; nt++) {
            float p0 = ex2(sc[nt][0] - mn0); sc[nt][0] = p0; s0 += p0;
            float p1 = ex2(sc[nt][1] - mn0); sc[nt][1] = p1; s0 += p1;
            float p2 = ex2(sc[nt][2] - mn1); sc[nt][2] = p2; s1 += p2;
            float p3 = ex2(sc[nt][3] - mn1); sc[nt][3] = p3; s1 += p3;
        }
        s0 += __shfl_xor_sync(0xffffffffu, s0, 1);
        s0 += __shfl_xor_sync(0xffffffffu, s0, 2);
        s1 += __shfl_xor_sync(0xffffffffu, s1, 1);
        s1 += __shfl_xor_sync(0xffffffffu, s1, 2);
        l0 = l0 * corr0 + s0;
        l1 = l1 * corr1 + s1;

        #pragma unroll
        for (int dt = 0; dt < 8; dt++) {
            oc[dt][0] *= corr0; oc[dt][1] *= corr0;
            oc[dt][2] *= corr1; oc[dt][3] *= corr1;
        }

        // ---- write P (tf32 bits) — warp-private rows ----
        #pragma unroll
        for (int nt = 0; nt < 8; nt++) {
            int col = nt * 8 + 2 * c;
            *(uint2*)&sPQ[(r0    ) * PQ_STR + col] =
                make_uint2(f2tf32(sc[nt][0]), f2tf32(sc[nt][1]));
            *(uint2*)&sPQ[(r0 + 8) * PQ_STR + col] =
                make_uint2(f2tf32(sc[nt][2]), f2tf32(sc[nt][3]));
        }
        __syncwarp();

        // ---- O += P @ V : 4 ks-pairs ----
        #pragma unroll
        for (int tp = 0; tp < 4; tp++) {
            const int kkE = tp * 16, kkO = tp * 16 + 8;
            unsigned pe[4], po[4];
            pe[0] = __float_as_uint(sPQ[(r0    ) * PQ_STR + kkE + c]);
            pe[1] = __float_as_uint(sPQ[(r0 + 8) * PQ_STR + kkE + c]);
            pe[2] = __float_as_uint(sPQ[(r0    ) * PQ_STR + kkE + c + 4]);
            pe[3] = __float_as_uint(sPQ[(r0 + 8) * PQ_STR + kkE + c + 4]);
            po[0] = __float_as_uint(sPQ[(r0    ) * PQ_STR + kkO + c]);
            po[1] = __float_as_uint(sPQ[(r0 + 8) * PQ_STR + kkO + c]);
            po[2] = __float_as_uint(sPQ[(r0    ) * PQ_STR + kkO + c + 4]);
            po[3] = __float_as_uint(sPQ[(r0 + 8) * PQ_STR + kkO + c + 4]);
            #pragma unroll
            for (int dt = 0; dt < 8; dt++) {
                uint4 vf = *(uint4*)&sVt[(dt * 8 + g) * VT_STR + tp * 16 + 4 * c];
                unsigned be[2] = {vf.x, vf.y}, bo[2] = {vf.z, vf.w};
                mma16n8k8(oc[dt], pe, be);
                mma16n8k8(oc[dt], po, bo);
            }
        }
    }

    // ---- epilogue ----
    const float inv0 = 1.f / l0, inv1 = 1.f / l1;
    const int t_0 = qb * 128 + r0;
    #pragma unroll
    for (int dt = 0; dt < 8; dt++) {
        int col = h * HD + dt * 8 + 2 * c;
        float2 o0 = make_float2(oc[dt][0] * inv0, oc[dt][1] * inv0);
        float2 o1 = make_float2(oc[dt][2] * inv1, oc[dt][3] * inv1);
        *(float2*)&y[((size_t)(b * T_SEQ + t_0)) * C_EMBD + col]     = o0;
        *(float2*)&y[((size_t)(b * T_SEQ + t_0 + 8)) * C_EMBD + col] = o1;
    }
}

// ---------------------------------------------------------------------------
extern "C" void kernel_launch(void* const* d_in, const int* in_sizes, int n_in,
                              void* d_out, int out_size)
{
    const float* x      = (const float*)d_in[0];
    const float* W_attn = (const float*)d_in[1];
    const float* b_attn = (const float*)d_in[2];
    const float* W_proj = (const float*)d_in[3];
    const float* b_proj = (const float*)d_in[4];
    float* out = (float*)d_out;

    float *qkv, *y;
    cudaGetSymbolAddress((void**)&qkv, g_qkv);
    cudaGetSymbolAddress((void**)&y,   g_y);

    cudaFuncSetAttribute(sgemm_tf32, cudaFuncAttributeMaxDynamicSharedMemorySize, GEMM_SMEM);
    cudaFuncSetAttribute(flash_attn_tf32, cudaFuncAttributeMaxDynamicSharedMemorySize, FA_SMEM);

    dim3 g1(3 * C_EMBD / 128, M_ROWS / 128);
    sgemm_tf32<<<g1, 256, GEMM_SMEM>>>(x, W_attn, b_attn, qkv, M_ROWS, 3 * C_EMBD, C_EMBD);

    flash_attn_tf32<<<dim3(T_SEQ / 128, BATCH * NH), 256, FA_SMEM>>>(qkv, y);

    dim3 g2(C_EMBD / 128, M_ROWS / 128);
    sgemm_tf32<<<g2, 256, GEMM_SMEM>>>(y, W_proj, b_proj, out, M_ROWS, C_EMBD, C_EMBD);
}

// round 5
// speedup vs baseline: 1.4345x; 1.4345x over previous
#include <cuda_runtime.h>
#include <math.h>

#define C_EMBD 768
#define NH     12
#define HD     64
#define T_SEQ  4096
#define BATCH  2
#define M_ROWS (BATCH * T_SEQ)   // 8192

__device__ float g_qkv[(size_t)BATCH * T_SEQ * 3 * C_EMBD]; // [B,T,3C]
__device__ float g_y  [(size_t)BATCH * T_SEQ * C_EMBD];     // [B,T,C]

__device__ __forceinline__ unsigned f2tf32(float x) {
    unsigned r;
    asm("cvt.rna.tf32.f32 %0, %1;" : "=r"(r) : "f"(x));
    return r;
}
__device__ __forceinline__ float ex2(float x) {
    float r;
    asm("ex2.approx.f32 %0, %1;" : "=f"(r) : "f"(x));
    return r;
}
__device__ __forceinline__ void mma16n8k8(float* c, const unsigned* a, const unsigned* b) {
    asm volatile(
        "mma.sync.aligned.m16n8k8.row.col.f32.tf32.tf32.f32 "
        "{%0,%1,%2,%3}, {%4,%5,%6,%7}, {%8,%9}, {%0,%1,%2,%3};\n"
        : "+f"(c[0]), "+f"(c[1]), "+f"(c[2]), "+f"(c[3])
        : "r"(a[0]), "r"(a[1]), "r"(a[2]), "r"(a[3]), "r"(b[0]), "r"(b[1]));
}
__device__ __forceinline__ unsigned smem_u32(const void* p) {
    return (unsigned)__cvta_generic_to_shared(p);
}
__device__ __forceinline__ void cp_async16(unsigned saddr, const void* g) {
    asm volatile("cp.async.cg.shared.global [%0], [%1], 16;\n" :: "r"(saddr), "l"(g));
}
#define CP_COMMIT() asm volatile("cp.async.commit_group;\n")
#define CP_WAIT(n)  asm volatile("cp.async.wait_group %0;\n" :: "n"(n))

// In-place vectorized fp32 -> tf32 of one 16-float chunk (16B granular).
__device__ __forceinline__ void cvt16_inplace(float* base) {
    #pragma unroll
    for (int j = 0; j < 4; j++) {
        float4 v = *(float4*)&base[4 * j];
        *(uint4*)&base[4 * j] =
            make_uint4(f2tf32(v.x), f2tf32(v.y), f2tf32(v.z), f2tf32(v.w));
    }
}

// ---------------------------------------------------------------------------
// TF32 GEMM + bias. 128x128 tile, BK=32, 256 thr = 8 warps (4M x 2N).
// cp.async double-buffered; after arrival one in-place cvt pass converts the
// whole stage to tf32; inner-loop fragment loads are raw LDS (no cvt).
// ---------------------------------------------------------------------------
#define ASTR 36
#define BSTR 136
#define GEMM_SMEM ((2 * 128 * ASTR + 2 * 32 * BSTR) * 4)

__global__ __launch_bounds__(256, 2) void sgemm_tf32(
    const float* __restrict__ A, const float* __restrict__ B,
    const float* __restrict__ bias, float* __restrict__ Cm,
    int M, int N, int K)
{
    extern __shared__ float sm[];
    float* As = sm;                    // 2 x [128][ASTR]
    float* Bs = sm + 2 * 128 * ASTR;   // 2 x [32][BSTR]

    const int tid  = threadIdx.x;
    const int warp = tid >> 5, lane = tid & 31;
    const int wm = warp & 3, wn = warp >> 2;
    const int g = lane >> 2, c = lane & 3;

    const int by = blockIdx.y, bx = blockIdx.x;
    const float* Ab = A + (size_t)by * 128 * K;
    const float* Bb = B + (size_t)bx * 128;

    float acc[2][8][4];
    #pragma unroll
    for (int mt = 0; mt < 2; mt++)
        #pragma unroll
        for (int nt = 0; nt < 8; nt++)
            #pragma unroll
            for (int r = 0; r < 4; r++) acc[mt][nt][r] = 0.f;

    const int am = tid >> 3, ak = (tid & 7) * 4;
    const int bk = tid >> 5, bn = (tid & 31) * 4;

    #define LOAD_STAGE(s, k0)                                                      \
        {                                                                          \
            _Pragma("unroll")                                                      \
            for (int i = 0; i < 4; i++) {                                          \
                cp_async16(smem_u32(&As[(s) * 128 * ASTR + (am + i * 32) * ASTR + ak]), \
                           &Ab[(size_t)(am + i * 32) * K + (k0) + ak]);            \
                cp_async16(smem_u32(&Bs[(s) * 32 * BSTR + (bk + i * 8) * BSTR + bn]),   \
                           &Bb[(size_t)((k0) + bk + i * 8) * N + bn]);             \
            }                                                                      \
        }

    LOAD_STAGE(0, 0);
    CP_COMMIT();

    const int NK = K / 32;
    for (int kt = 0; kt < NK; kt++) {
        __syncthreads();   // prior-iter reads of the buffer being overwritten done
        if (kt + 1 < NK) LOAD_STAGE((kt + 1) & 1, (kt + 1) * 32);
        CP_COMMIT();
        CP_WAIT(1);        // stage kt arrived; stage kt+1 in flight
        __syncthreads();

        // ---- in-place cvt of stage kt (A: 128x32, B: 32x128) ----
        cvt16_inplace(&As[(kt & 1) * 128 * ASTR + (tid >> 1) * ASTR + (tid & 1) * 16]);
        cvt16_inplace(&Bs[(kt & 1) * 32 * BSTR + (tid & 31) * BSTR + (tid >> 5) * 16]);
        __syncthreads();

        const unsigned* Au = (const unsigned*)&As[(kt & 1) * 128 * ASTR];
        const unsigned* Bu = (const unsigned*)&Bs[(kt & 1) * 32 * BSTR];

        #pragma unroll
        for (int ks = 0; ks < 4; ks++) {
            const int kk = ks * 8;
            unsigned a[2][4], b[8][2];
            #pragma unroll
            for (int mt = 0; mt < 2; mt++) {
                int m0 = wm * 32 + mt * 16;
                a[mt][0] = Au[(m0 + g    ) * ASTR + kk + c];
                a[mt][1] = Au[(m0 + g + 8) * ASTR + kk + c];
                a[mt][2] = Au[(m0 + g    ) * ASTR + kk + c + 4];
                a[mt][3] = Au[(m0 + g + 8) * ASTR + kk + c + 4];
            }
            #pragma unroll
            for (int nt = 0; nt < 8; nt++) {
                int n0 = wn * 64 + nt * 8;
                b[nt][0] = Bu[(kk + c    ) * BSTR + n0 + g];
                b[nt][1] = Bu[(kk + c + 4) * BSTR + n0 + g];
            }
            #pragma unroll
            for (int mt = 0; mt < 2; mt++)
                #pragma unroll
                for (int nt = 0; nt < 8; nt++)
                    mma16n8k8(acc[mt][nt], a[mt], b[nt]);
        }
    }

    #pragma unroll
    for (int mt = 0; mt < 2; mt++) {
        #pragma unroll
        for (int nt = 0; nt < 8; nt++) {
            int row0 = by * 128 + wm * 32 + mt * 16 + g;
            int col  = bx * 128 + wn * 64 + nt * 8 + 2 * c;
            float2 bv = *(const float2*)&bias[col];
            float2 o0 = make_float2(acc[mt][nt][0] + bv.x, acc[mt][nt][1] + bv.y);
            float2 o1 = make_float2(acc[mt][nt][2] + bv.x, acc[mt][nt][3] + bv.y);
            *(float2*)&Cm[(size_t)row0 * N + col]       = o0;
            *(float2*)&Cm[(size_t)(row0 + 8) * N + col] = o1;
        }
    }
}

// ---------------------------------------------------------------------------
// Flash attention, TF32. Br=128, Bc=64, 256 thr = 8 warps (16 rows each).
// K and V both double-buffered via cp.async; one in-place cvt pass per tile;
// fragment loads raw LDS. P warp-private; ex2 with log2e folded into Q scale.
// ---------------------------------------------------------------------------
#define KS_STR 68
#define VS_STR 68
#define PQ_STR 68
#define FA_SMEM ((2 * 64 * KS_STR + 2 * 64 * VS_STR + 128 * PQ_STR) * 4)

__global__ __launch_bounds__(256, 2) void flash_attn_tf32(
    const float* __restrict__ qkv, float* __restrict__ y)
{
    extern __shared__ float sm[];
    float* sK  = sm;                      // 2 x [64][KS_STR]
    float* sV  = sK + 2 * 64 * KS_STR;    // 2 x [64][VS_STR]
    float* sPQ = sV + 2 * 64 * VS_STR;    // [128][PQ_STR] (Q staging, then P)

    const int tid  = threadIdx.x;
    const int warp = tid >> 5, lane = tid & 31;
    const int g = lane >> 2, c = lane & 3;
    const int qb = blockIdx.x;
    const int bh = blockIdx.y;
    const int b = bh / NH, h = bh % NH;

    const size_t rowstr = 3 * C_EMBD;
    const float* qp = qkv + ((size_t)(b * T_SEQ + qb * 128)) * rowstr + h * HD;
    const float* kp = qkv + ((size_t)b * T_SEQ) * rowstr + C_EMBD + h * HD;
    const float* vp = qkv + ((size_t)b * T_SEQ) * rowstr + 2 * C_EMBD + h * HD;
    const float qscale = 0.125f * 1.4426950408889634f; // 1/sqrt(64) * log2(e)

    const int lr = tid >> 4, ld4 = (tid & 15) << 2;
    #define LOAD_K(s, t0)                                                           \
        {                                                                           \
            _Pragma("unroll")                                                       \
            for (int i = 0; i < 4; i++)                                             \
                cp_async16(smem_u32(&sK[(s) * 64 * KS_STR + (lr + i * 16) * KS_STR + ld4]), \
                           &kp[(size_t)((t0) + lr + i * 16) * rowstr + ld4]);       \
        }
    #define LOAD_V(s, t0)                                                           \
        {                                                                           \
            _Pragma("unroll")                                                       \
            for (int i = 0; i < 4; i++)                                             \
                cp_async16(smem_u32(&sV[(s) * 64 * VS_STR + (lr + i * 16) * VS_STR + ld4]), \
                           &vp[(size_t)((t0) + lr + i * 16) * rowstr + ld4]);       \
        }

    LOAD_K(0, 0);
    LOAD_V(0, 0);
    CP_COMMIT();

    // ---- stage Q, pull A-fragments (scaled tf32) ----
    #pragma unroll
    for (int i = 0; i < 8; i++) {
        int idx = tid + i * 256;
        int row = idx >> 4, d4 = (idx & 15) << 2;
        *(float4*)&sPQ[row * PQ_STR + d4] = *(const float4*)&qp[(size_t)row * rowstr + d4];
    }
    __syncthreads();
    const int r0 = 16 * warp + g;
    unsigned qa[8][4];
    #pragma unroll
    for (int ks = 0; ks < 8; ks++) {
        int kk = ks * 8;
        qa[ks][0] = f2tf32(sPQ[(r0    ) * PQ_STR + kk + c]     * qscale);
        qa[ks][1] = f2tf32(sPQ[(r0 + 8) * PQ_STR + kk + c]     * qscale);
        qa[ks][2] = f2tf32(sPQ[(r0    ) * PQ_STR + kk + c + 4] * qscale);
        qa[ks][3] = f2tf32(sPQ[(r0 + 8) * PQ_STR + kk + c + 4] * qscale);
    }

    float m0r = -INFINITY, m1r = -INFINITY, l0 = 0.f, l1 = 0.f;
    float oc[8][4];
    #pragma unroll
    for (int dt = 0; dt < 8; dt++)
        #pragma unroll
        for (int r = 0; r < 4; r++) oc[dt][r] = 0.f;

    const int NT = T_SEQ / 64;
    for (int t = 0; t < NT; t++) {
        __syncthreads();   // prior-iter reads of buffers being overwritten done
        if (t + 1 < NT) { LOAD_K((t + 1) & 1, (t + 1) * 64); LOAD_V((t + 1) & 1, (t + 1) * 64); }
        CP_COMMIT();
        CP_WAIT(1);        // tile t arrived; tile t+1 in flight
        __syncthreads();

        // ---- in-place cvt of K(t), V(t) (64x64 each; thread = row, 16-col grp) ----
        {
            const int row = tid & 63, q = tid >> 6;
            cvt16_inplace(&sK[(t & 1) * 64 * KS_STR + row * KS_STR + q * 16]);
            cvt16_inplace(&sV[(t & 1) * 64 * VS_STR + row * VS_STR + q * 16]);
        }
        __syncthreads();

        const unsigned* Ku = (const unsigned*)&sK[(t & 1) * 64 * KS_STR];
        const unsigned* Vu = (const unsigned*)&sV[(t & 1) * 64 * VS_STR];

        // ---- S = Q @ K^T ----
        float sc[8][4];
        #pragma unroll
        for (int nt = 0; nt < 8; nt++)
            #pragma unroll
            for (int r = 0; r < 4; r++) sc[nt][r] = 0.f;

        #pragma unroll
        for (int ks = 0; ks < 8; ks++) {
            const int kk = ks * 8;
            unsigned bfr[8][2];
            #pragma unroll
            for (int nt = 0; nt < 8; nt++) {
                bfr[nt][0] = Ku[(nt * 8 + g) * KS_STR + kk + c];
                bfr[nt][1] = Ku[(nt * 8 + g) * KS_STR + kk + c + 4];
            }
            #pragma unroll
            for (int nt = 0; nt < 8; nt++)
                mma16n8k8(sc[nt], qa[ks], bfr[nt]);
        }

        // ---- online softmax (base-2) ----
        float rm0 = -INFINITY, rm1 = -INFINITY;
        #pragma unroll
        for (int nt = 0; nt < 8; nt++) {
            rm0 = fmaxf(rm0, fmaxf(sc[nt][0], sc[nt][1]));
            rm1 = fmaxf(rm1, fmaxf(sc[nt][2], sc[nt][3]));
        }
        rm0 = fmaxf(rm0, __shfl_xor_sync(0xffffffffu, rm0, 1));
        rm0 = fmaxf(rm0, __shfl_xor_sync(0xffffffffu, rm0, 2));
        rm1 = fmaxf(rm1, __shfl_xor_sync(0xffffffffu, rm1, 1));
        rm1 = fmaxf(rm1, __shfl_xor_sync(0xffffffffu, rm1, 2));

        float mn0 = fmaxf(m0r, rm0), mn1 = fmaxf(m1r, rm1);
        float corr0 = ex2(m0r - mn0), corr1 = ex2(m1r - mn1);
        m0r = mn0; m1r = mn1;

        float s0 = 0.f, s1 = 0.f;
        #pragma unroll
        for (int nt = 0; nt < 8; nt++) {
            float p0 = ex2(sc[nt][0] - mn0); sc[nt][0] = p0; s0 += p0;
            float p1 = ex2(sc[nt][1] - mn0); sc[nt][1] = p1; s0 += p1;
            float p2 = ex2(sc[nt][2] - mn1); sc[nt][2] = p2; s1 += p2;
            float p3 = ex2(sc[nt][3] - mn1); sc[nt][3] = p3; s1 += p3;
        }
        s0 += __shfl_xor_sync(0xffffffffu, s0, 1);
        s0 += __shfl_xor_sync(0xffffffffu, s0, 2);
        s1 += __shfl_xor_sync(0xffffffffu, s1, 1);
        s1 += __shfl_xor_sync(0xffffffffu, s1, 2);
        l0 = l0 * corr0 + s0;
        l1 = l1 * corr1 + s1;

        #pragma unroll
        for (int dt = 0; dt < 8; dt++) {
            oc[dt][0] *= corr0; oc[dt][1] *= corr0;
            oc[dt][2] *= corr1; oc[dt][3] *= corr1;
        }

        // ---- write P (tf32 bits) — warp-private rows ----
        #pragma unroll
        for (int nt = 0; nt < 8; nt++) {
            int col = nt * 8 + 2 * c;
            *(uint2*)&sPQ[(r0    ) * PQ_STR + col] =
                make_uint2(f2tf32(sc[nt][0]), f2tf32(sc[nt][1]));
            *(uint2*)&sPQ[(r0 + 8) * PQ_STR + col] =
                make_uint2(f2tf32(sc[nt][2]), f2tf32(sc[nt][3]));
        }
        __syncwarp();

        // ---- O += P @ V ----
        #pragma unroll
        for (int ks = 0; ks < 8; ks++) {
            const int kk = ks * 8;
            unsigned pa[4];
            pa[0] = __float_as_uint(sPQ[(r0    ) * PQ_STR + kk + c]);
            pa[1] = __float_as_uint(sPQ[(r0 + 8) * PQ_STR + kk + c]);
            pa[2] = __float_as_uint(sPQ[(r0    ) * PQ_STR + kk + c + 4]);
            pa[3] = __float_as_uint(sPQ[(r0 + 8) * PQ_STR + kk + c + 4]);
            #pragma unroll
            for (int dt = 0; dt < 8; dt++) {
                unsigned vb[2];
                vb[0] = Vu[(kk + c    ) * VS_STR + dt * 8 + g];
                vb[1] = Vu[(kk + c + 4) * VS_STR + dt * 8 + g];
                mma16n8k8(oc[dt], pa, vb);
            }
        }
    }

    // ---- epilogue ----
    const float inv0 = 1.f / l0, inv1 = 1.f / l1;
    const int t_0 = qb * 128 + r0;
    #pragma unroll
    for (int dt = 0; dt < 8; dt++) {
        int col = h * HD + dt * 8 + 2 * c;
        float2 o0 = make_float2(oc[dt][0] * inv0, oc[dt][1] * inv0);
        float2 o1 = make_float2(oc[dt][2] * inv1, oc[dt][3] * inv1);
        *(float2*)&y[((size_t)(b * T_SEQ + t_0)) * C_EMBD + col]     = o0;
        *(float2*)&y[((size_t)(b * T_SEQ + t_0 + 8)) * C_EMBD + col] = o1;
    }
}

// ---------------------------------------------------------------------------
extern "C" void kernel_launch(void* const* d_in, const int* in_sizes, int n_in,
                              void* d_out, int out_size)
{
    const float* x      = (const float*)d_in[0];
    const float* W_attn = (const float*)d_in[1];
    const float* b_attn = (const float*)d_in[2];
    const float* W_proj = (const float*)d_in[3];
    const float* b_proj = (const float*)d_in[4];
    float* out = (float*)d_out;

    float *qkv, *y;
    cudaGetSymbolAddress((void**)&qkv, g_qkv);
    cudaGetSymbolAddress((void**)&y,   g_y);

    cudaFuncSetAttribute(sgemm_tf32, cudaFuncAttributeMaxDynamicSharedMemorySize, GEMM_SMEM);
    cudaFuncSetAttribute(flash_attn_tf32, cudaFuncAttributeMaxDynamicSharedMemorySize, FA_SMEM);

    dim3 g1(3 * C_EMBD / 128, M_ROWS / 128);
    sgemm_tf32<<<g1, 256, GEMM_SMEM>>>(x, W_attn, b_attn, qkv, M_ROWS, 3 * C_EMBD, C_EMBD);

    flash_attn_tf32<<<dim3(T_SEQ / 128, BATCH * NH), 256, FA_SMEM>>>(qkv, y);

    dim3 g2(C_EMBD / 128, M_ROWS / 128);
    sgemm_tf32<<<g2, 256, GEMM_SMEM>>>(y, W_proj, b_proj, out, M_ROWS, C_EMBD, C_EMBD);
}

// round 6
// speedup vs baseline: 1.8858x; 1.3146x over previous
#include <cuda_runtime.h>
#include <math.h>

#define C_EMBD 768
#define NH     12
#define HD     64
#define T_SEQ  4096
#define BATCH  2
#define M_ROWS (BATCH * T_SEQ)   // 8192

// Scratch (no cudaMalloc allowed)
__device__ float g_xc [(size_t)M_ROWS * C_EMBD];          // x, tf32 bits, perm cols
__device__ float g_wta[(size_t)3 * C_EMBD * C_EMBD];      // W_attn^T [N][K], tf32, perm k
__device__ float g_wpt[(size_t)C_EMBD * C_EMBD];          // W_proj^T [N][K], tf32, perm k
__device__ float g_qkv[(size_t)M_ROWS * 3 * C_EMBD];      // q,k regions: tf32 bits, perm cols
__device__ float g_vt [(size_t)BATCH * NH * HD * T_SEQ];  // V^T [b][h][d][T], tf32, perm keys
__device__ float g_y  [(size_t)M_ROWS * C_EMBD];          // attn out, tf32 bits, perm cols

__device__ __forceinline__ unsigned f2tf32(float x) {
    unsigned r;
    asm("cvt.rna.tf32.f32 %0, %1;" : "=r"(r) : "f"(x));
    return r;
}
__device__ __forceinline__ float ex2(float x) {
    float r;
    asm("ex2.approx.f32 %0, %1;" : "=f"(r) : "f"(x));
    return r;
}
__device__ __forceinline__ void mma16n8k8(float* c, const unsigned* a, const unsigned* b) {
    asm volatile(
        "mma.sync.aligned.m16n8k8.row.col.f32.tf32.tf32.f32 "
        "{%0,%1,%2,%3}, {%4,%5,%6,%7}, {%8,%9}, {%0,%1,%2,%3};\n"
        : "+f"(c[0]), "+f"(c[1]), "+f"(c[2]), "+f"(c[3])
        : "r"(a[0]), "r"(a[1]), "r"(a[2]), "r"(a[3]), "r"(b[0]), "r"(b[1]));
}
__device__ __forceinline__ unsigned smem_u32(const void* p) {
    return (unsigned)__cvta_generic_to_shared(p);
}
__device__ __forceinline__ void cp_async16(unsigned saddr, const void* g) {
    asm volatile("cp.async.cg.shared.global [%0], [%1], 16;\n" :: "r"(saddr), "l"(g));
}
#define CP_COMMIT() asm volatile("cp.async.commit_group;\n")
#define CP_WAIT(n)  asm volatile("cp.async.wait_group %0;\n" :: "n"(n))

// 16-group permutation: orig col j -> position 4*(j&3) + ((j>>2)&3) within group.
// pos 4i+j' holds orig col i+4j' => one LDS.128 yields fragments for 2 k-steps.
__device__ __forceinline__ int perm16(int j) {
    return (j & ~15) | ((j & 3) << 2) | ((j >> 2) & 3);
}

// ---------------------------------------------------------------------------
// Prepass 1: elementwise fp32 -> tf32 bits with 16-group column permutation.
// ---------------------------------------------------------------------------
__global__ void cvt_perm_kernel(const float* __restrict__ in, float* __restrict__ out,
                                int n4, int cols4)
{
    int idx = blockIdx.x * blockDim.x + threadIdx.x;
    if (idx >= n4) return;
    float4 v = ((const float4*)in)[idx];
    int col4 = (idx % cols4) * 4;
    size_t rowbase = (size_t)(idx / cols4) * (size_t)(cols4 * 4);
    int b16 = col4 & ~15, j = (col4 >> 2) & 3;
    out[rowbase + b16 + 0  + j] = __uint_as_float(f2tf32(v.x));
    out[rowbase + b16 + 4  + j] = __uint_as_float(f2tf32(v.y));
    out[rowbase + b16 + 8  + j] = __uint_as_float(f2tf32(v.z));
    out[rowbase + b16 + 12 + j] = __uint_as_float(f2tf32(v.w));
}

// ---------------------------------------------------------------------------
// Prepass 2: W[K][N] -> Wt[N][K] transpose + tf32 + perm-k. 32x32 smem tiles.
// ---------------------------------------------------------------------------
__global__ void tr_cvt_perm_kernel(const float* __restrict__ W, float* __restrict__ Wt,
                                   int K, int N)
{
    __shared__ float tile[32][33];
    int k0 = blockIdx.y * 32, n0 = blockIdx.x * 32;
    int tx = threadIdx.x, ty = threadIdx.y;
    #pragma unroll
    for (int r = 0; r < 4; r++)
        tile[ty + 8 * r][tx] = W[(size_t)(k0 + ty + 8 * r) * N + n0 + tx];
    __syncthreads();
    int kp = (tx & 16) | ((tx & 3) << 2) | ((tx >> 2) & 3);
    #pragma unroll
    for (int r = 0; r < 4; r++) {
        int n = ty + 8 * r;
        Wt[(size_t)(n0 + n) * K + k0 + kp] = __uint_as_float(f2tf32(tile[tx][n]));
    }
}

// ---------------------------------------------------------------------------
// TF32 GEMM + bias. A[M][K] perm-k tf32 bits, B=Wt[N][K] perm-k tf32 bits.
// 128x128 tile, BK=32, 256 thr = 8 warps (4M x 2N). LDS.128-only fragments.
// MODE 0: plain fp32 out. MODE 1: qkv epilogue (q/k perm tf32; v -> Vt).
// ---------------------------------------------------------------------------
#define TSTR 48
#define GEMM_SMEM (2 * 128 * TSTR * 2 * 4)

template<int MODE>
__global__ __launch_bounds__(256, 2) void gemm_tf32(
    const float* __restrict__ A, const float* __restrict__ B,
    const float* __restrict__ bias, float* __restrict__ Cm,
    float* __restrict__ Vt, int M, int N, int K)
{
    extern __shared__ float sm[];
    float* As = sm;                  // 2 x [128][TSTR]
    float* Bs = sm + 2 * 128 * TSTR; // 2 x [128][TSTR]

    const int tid  = threadIdx.x;
    const int warp = tid >> 5, lane = tid & 31;
    const int wm = warp & 3, wn = warp >> 2;
    const int g = lane >> 2, c = lane & 3;

    const int by = blockIdx.y, bx = blockIdx.x;
    const float* Ab = A + (size_t)by * 128 * K;
    const float* Bb = B + (size_t)bx * 128 * K;

    float acc[2][8][4];
    #pragma unroll
    for (int mt = 0; mt < 2; mt++)
        #pragma unroll
        for (int nt = 0; nt < 8; nt++)
            #pragma unroll
            for (int r = 0; r < 4; r++) acc[mt][nt][r] = 0.f;

    // 1024 16B chunks each for A and B per stage: cid -> row=cid>>3, col4=(cid&7)*4
    #define LOAD_STAGE(s, k0)                                                     \
        {                                                                         \
            _Pragma("unroll")                                                     \
            for (int i = 0; i < 4; i++) {                                         \
                int cid = tid + i * 256;                                          \
                int row = cid >> 3, c4 = (cid & 7) * 4;                           \
                cp_async16(smem_u32(&As[(s) * 128 * TSTR + row * TSTR + c4]),     \
                           &Ab[(size_t)row * K + (k0) + c4]);                     \
                cp_async16(smem_u32(&Bs[(s) * 128 * TSTR + row * TSTR + c4]),     \
                           &Bb[(size_t)row * K + (k0) + c4]);                     \
            }                                                                     \
        }

    LOAD_STAGE(0, 0);
    CP_COMMIT();

    const int NK = K / 32;
    for (int kt = 0; kt < NK; kt++) {
        __syncthreads();   // prior-iter reads of the buffer being overwritten done
        if (kt + 1 < NK) LOAD_STAGE((kt + 1) & 1, (kt + 1) * 32);
        CP_COMMIT();
        CP_WAIT(1);        // stage kt arrived
        __syncthreads();

        const float* Asb = &As[(kt & 1) * 128 * TSTR];
        const float* Bsb = &Bs[(kt & 1) * 128 * TSTR];

        #pragma unroll
        for (int tp = 0; tp < 2; tp++) {
            unsigned ae[2][4], ao[2][4];
            #pragma unroll
            for (int mt = 0; mt < 2; mt++) {
                int m0 = wm * 32 + mt * 16;
                uint4 f0 = *(const uint4*)&Asb[(m0 + g    ) * TSTR + tp * 16 + 4 * c];
                uint4 f1 = *(const uint4*)&Asb[(m0 + g + 8) * TSTR + tp * 16 + 4 * c];
                ae[mt][0] = f0.x; ae[mt][1] = f1.x; ae[mt][2] = f0.y; ae[mt][3] = f1.y;
                ao[mt][0] = f0.z; ao[mt][1] = f1.z; ao[mt][2] = f0.w; ao[mt][3] = f1.w;
            }
            #pragma unroll
            for (int nt = 0; nt < 8; nt++) {
                int n0 = wn * 64 + nt * 8;
                uint4 fb = *(const uint4*)&Bsb[(n0 + g) * TSTR + tp * 16 + 4 * c];
                unsigned be[2] = {fb.x, fb.y}, bo[2] = {fb.z, fb.w};
                mma16n8k8(acc[0][nt], ae[0], be);
                mma16n8k8(acc[1][nt], ae[1], be);
                mma16n8k8(acc[0][nt], ao[0], bo);
                mma16n8k8(acc[1][nt], ao[1], bo);
            }
        }
    }

    #pragma unroll
    for (int mt = 0; mt < 2; mt++) {
        #pragma unroll
        for (int nt = 0; nt < 8; nt++) {
            int row0 = by * 128 + wm * 32 + mt * 16 + g;
            int col  = bx * 128 + wn * 64 + nt * 8 + 2 * c;
            float2 bv = *(const float2*)&bias[col];
            float v00 = acc[mt][nt][0] + bv.x, v01 = acc[mt][nt][1] + bv.y;
            float v10 = acc[mt][nt][2] + bv.x, v11 = acc[mt][nt][3] + bv.y;
            if (MODE == 0) {
                *(float2*)&Cm[(size_t)row0 * N + col]       = make_float2(v00, v01);
                *(float2*)&Cm[(size_t)(row0 + 8) * N + col] = make_float2(v10, v11);
            } else {
                unsigned u00 = f2tf32(v00), u01 = f2tf32(v01);
                unsigned u10 = f2tf32(v10), u11 = f2tf32(v11);
                if (col < 2 * C_EMBD) {   // q, k regions: perm cols, tf32 bits
                    int p0 = perm16(col), p1 = perm16(col + 1);
                    Cm[(size_t)row0 * N + p0]       = __uint_as_float(u00);
                    Cm[(size_t)row0 * N + p1]       = __uint_as_float(u01);
                    Cm[(size_t)(row0 + 8) * N + p0] = __uint_as_float(u10);
                    Cm[(size_t)(row0 + 8) * N + p1] = __uint_as_float(u11);
                } else {                  // v region: transpose to Vt, perm keys
                    int cv = col - 2 * C_EMBD;
                    int h = cv >> 6, d = cv & 63;
                    int bb = row0 >> 12;
                    int tt0 = perm16(row0 & 4095), tt1 = perm16((row0 + 8) & 4095);
                    size_t base = ((size_t)(bb * NH + h) * HD + d) * T_SEQ;
                    Vt[base + tt0]         = __uint_as_float(u00);
                    Vt[base + T_SEQ + tt0] = __uint_as_float(u01);
                    Vt[base + tt1]         = __uint_as_float(u10);
                    Vt[base + T_SEQ + tt1] = __uint_as_float(u11);
                }
            }
        }
    }
}

// ---------------------------------------------------------------------------
// Flash attention, TF32, pre-converted inputs. Br=128, Bc=64, 256 thr, 8 warps.
// K double-buffered, V single-buffered (awaited post-softmax). No cvt, no
// transpose in the loop: LDS.128 fragments from permuted layouts.
// ---------------------------------------------------------------------------
#define KSTR  80
#define VSTR  80
#define PQSTR 68
#define FA_SMEM ((2 * 64 * KSTR + 64 * VSTR + 128 * PQSTR) * 4)

__global__ __launch_bounds__(256, 2) void flash_attn_tf32(
    const float* __restrict__ qkv, const float* __restrict__ vt, float* __restrict__ y)
{
    extern __shared__ float sm[];
    float* sK  = sm;                     // 2 x [64][KSTR]
    float* sV  = sK + 2 * 64 * KSTR;     // [64][VSTR]  (rows = d, cols = keys perm)
    float* sPQ = sV + 64 * VSTR;         // [128][PQSTR] (Q staging, then P)

    const int tid  = threadIdx.x;
    const int warp = tid >> 5, lane = tid & 31;
    const int g = lane >> 2, c = lane & 3;
    const int qb = blockIdx.x;
    const int bh = blockIdx.y;
    const int b = bh / NH, h = bh % NH;

    const float* qp  = qkv + (size_t)(b * T_SEQ + qb * 128) * (3 * C_EMBD) + h * HD;
    const float* kp  = qkv + (size_t)b * T_SEQ * (3 * C_EMBD) + C_EMBD + h * HD;
    const float* vtp = vt + (size_t)(b * NH + h) * HD * T_SEQ;
    const float qscale = 0.125f * 1.4426950408889634f; // 1/sqrt(64) * log2(e)

    #define LOAD_K(s, t0)                                                          \
        {                                                                          \
            _Pragma("unroll")                                                      \
            for (int i = 0; i < 4; i++) {                                          \
                int cid = tid + i * 256;                                           \
                int row = cid >> 4, c4 = (cid & 15) * 4;                           \
                cp_async16(smem_u32(&sK[(s) * 64 * KSTR + row * KSTR + c4]),       \
                           &kp[(size_t)((t0) + row) * (3 * C_EMBD) + c4]);         \
            }                                                                      \
        }
    #define LOAD_V(t0)                                                             \
        {                                                                          \
            _Pragma("unroll")                                                      \
            for (int i = 0; i < 4; i++) {                                          \
                int cid = tid + i * 256;                                           \
                int row = cid >> 4, c4 = (cid & 15) * 4;                           \
                cp_async16(smem_u32(&sV[row * VSTR + c4]),                         \
                           &vtp[(size_t)row * T_SEQ + (t0) + c4]);                 \
            }                                                                      \
        }

    // ---- stage Q tile (permuted tf32 bits) ----
    #pragma unroll
    for (int i = 0; i < 8; i++) {
        int cid = tid + i * 256;
        int row = cid >> 4, c4 = (cid & 15) * 4;
        cp_async16(smem_u32(&sPQ[row * PQSTR + c4]),
                   &qp[(size_t)row * (3 * C_EMBD) + c4]);
    }
    CP_COMMIT();
    LOAD_K(0, 0);
    CP_COMMIT();
    CP_WAIT(1);          // Q arrived (K0 in flight)
    __syncthreads();

    // ---- gather Q fragments (scale + single re-cvt) ----
    const int r0 = 16 * warp + g;
    unsigned qa[8][4];
    #pragma unroll
    for (int t = 0; t < 4; t++) {
        uint4 f0 = *(const uint4*)&sPQ[(r0    ) * PQSTR + t * 16 + 4 * c];
        uint4 f1 = *(const uint4*)&sPQ[(r0 + 8) * PQSTR + t * 16 + 4 * c];
        qa[2 * t][0] = f2tf32(__uint_as_float(f0.x) * qscale);
        qa[2 * t][1] = f2tf32(__uint_as_float(f1.x) * qscale);
        qa[2 * t][2] = f2tf32(__uint_as_float(f0.y) * qscale);
        qa[2 * t][3] = f2tf32(__uint_as_float(f1.y) * qscale);
        qa[2 * t + 1][0] = f2tf32(__uint_as_float(f0.z) * qscale);
        qa[2 * t + 1][1] = f2tf32(__uint_as_float(f1.z) * qscale);
        qa[2 * t + 1][2] = f2tf32(__uint_as_float(f0.w) * qscale);
        qa[2 * t + 1][3] = f2tf32(__uint_as_float(f1.w) * qscale);
    }

    float m0r = -INFINITY, m1r = -INFINITY, l0 = 0.f, l1 = 0.f;
    float oc[8][4];
    #pragma unroll
    for (int dt = 0; dt < 8; dt++)
        #pragma unroll
        for (int r = 0; r < 4; r++) oc[dt][r] = 0.f;

    const int NT = T_SEQ / 64;
    for (int t = 0; t < NT; t++) {
        __syncthreads();                    // prior-iter smem reads done
        LOAD_V(t * 64);
        CP_COMMIT();                        // group: V(t)
        if (t + 1 < NT) LOAD_K((t + 1) & 1, (t + 1) * 64);
        CP_COMMIT();                        // group: K(t+1) (possibly empty)
        CP_WAIT(2);                         // K(t) arrived
        __syncthreads();

        const float* Kb = &sK[(t & 1) * 64 * KSTR];

        // ---- S = Q @ K^T : LDS.128-only fragments ----
        float sc[8][4];
        #pragma unroll
        for (int nt = 0; nt < 8; nt++)
            #pragma unroll
            for (int r = 0; r < 4; r++) sc[nt][r] = 0.f;

        #pragma unroll
        for (int tp = 0; tp < 4; tp++) {
            #pragma unroll
            for (int nt = 0; nt < 8; nt++) {
                uint4 kf = *(const uint4*)&Kb[(nt * 8 + g) * KSTR + tp * 16 + 4 * c];
                unsigned be[2] = {kf.x, kf.y}, bo[2] = {kf.z, kf.w};
                mma16n8k8(sc[nt], qa[2 * tp],     be);
                mma16n8k8(sc[nt], qa[2 * tp + 1], bo);
            }
        }

        // ---- online softmax (base-2) ----
        float rm0 = -INFINITY, rm1 = -INFINITY;
        #pragma unroll
        for (int nt = 0; nt < 8; nt++) {
            rm0 = fmaxf(rm0, fmaxf(sc[nt][0], sc[nt][1]));
            rm1 = fmaxf(rm1, fmaxf(sc[nt][2], sc[nt][3]));
        }
        rm0 = fmaxf(rm0, __shfl_xor_sync(0xffffffffu, rm0, 1));
        rm0 = fmaxf(rm0, __shfl_xor_sync(0xffffffffu, rm0, 2));
        rm1 = fmaxf(rm1, __shfl_xor_sync(0xffffffffu, rm1, 1));
        rm1 = fmaxf(rm1, __shfl_xor_sync(0xffffffffu, rm1, 2));

        float mn0 = fmaxf(m0r, rm0), mn1 = fmaxf(m1r, rm1);
        float corr0 = ex2(m0r - mn0), corr1 = ex2(m1r - mn1);
        m0r = mn0; m1r = mn1;

        float s0 = 0.f, s1 = 0.f;
        #pragma unroll
        for (int nt = 0; nt < 8; nt++) {
            float p0 = ex2(sc[nt][0] - mn0); sc[nt][0] = p0; s0 += p0;
            float p1 = ex2(sc[nt][1] - mn0); sc[nt][1] = p1; s0 += p1;
            float p2 = ex2(sc[nt][2] - mn1); sc[nt][2] = p2; s1 += p2;
            float p3 = ex2(sc[nt][3] - mn1); sc[nt][3] = p3; s1 += p3;
        }
        s0 += __shfl_xor_sync(0xffffffffu, s0, 1);
        s0 += __shfl_xor_sync(0xffffffffu, s0, 2);
        s1 += __shfl_xor_sync(0xffffffffu, s1, 1);
        s1 += __shfl_xor_sync(0xffffffffu, s1, 2);
        l0 = l0 * corr0 + s0;
        l1 = l1 * corr1 + s1;

        #pragma unroll
        for (int dt = 0; dt < 8; dt++) {
            oc[dt][0] *= corr0; oc[dt][1] *= corr0;
            oc[dt][2] *= corr1; oc[dt][3] *= corr1;
        }

        // ---- write P (tf32 bits) — warp-private rows ----
        #pragma unroll
        for (int nt = 0; nt < 8; nt++) {
            int col = nt * 8 + 2 * c;
            *(uint2*)&sPQ[(r0    ) * PQSTR + col] =
                make_uint2(f2tf32(sc[nt][0]), f2tf32(sc[nt][1]));
            *(uint2*)&sPQ[(r0 + 8) * PQSTR + col] =
                make_uint2(f2tf32(sc[nt][2]), f2tf32(sc[nt][3]));
        }
        __syncwarp();

        CP_WAIT(1);          // V(t) arrived (K(t+1) may still be in flight)
        __syncthreads();

        // ---- O += P @ V : Vt rows = d, LDS.128 key-pairs ----
        #pragma unroll
        for (int tp = 0; tp < 4; tp++) {
            const int kkE = tp * 16, kkO = tp * 16 + 8;
            unsigned pe[4], po[4];
            pe[0] = __float_as_uint(sPQ[(r0    ) * PQSTR + kkE + c]);
            pe[1] = __float_as_uint(sPQ[(r0 + 8) * PQSTR + kkE + c]);
            pe[2] = __float_as_uint(sPQ[(r0    ) * PQSTR + kkE + c + 4]);
            pe[3] = __float_as_uint(sPQ[(r0 + 8) * PQSTR + kkE + c + 4]);
            po[0] = __float_as_uint(sPQ[(r0    ) * PQSTR + kkO + c]);
            po[1] = __float_as_uint(sPQ[(r0 + 8) * PQSTR + kkO + c]);
            po[2] = __float_as_uint(sPQ[(r0    ) * PQSTR + kkO + c + 4]);
            po[3] = __float_as_uint(sPQ[(r0 + 8) * PQSTR + kkO + c + 4]);
            #pragma unroll
            for (int dt = 0; dt < 8; dt++) {
                uint4 vf = *(const uint4*)&sV[(dt * 8 + g) * VSTR + tp * 16 + 4 * c];
                unsigned be[2] = {vf.x, vf.y}, bo[2] = {vf.z, vf.w};
                mma16n8k8(oc[dt], pe, be);
                mma16n8k8(oc[dt], po, bo);
            }
        }
    }

    // ---- epilogue: normalize, write y as permuted tf32 bits ----
    const float inv0 = 1.f / l0, inv1 = 1.f / l1;
    const int t_0 = qb * 128 + r0;
    const size_t rb0 = (size_t)(b * T_SEQ + t_0) * C_EMBD;
    const size_t rb1 = (size_t)(b * T_SEQ + t_0 + 8) * C_EMBD;
    #pragma unroll
    for (int dt = 0; dt < 8; dt++) {
        int colj = h * HD + dt * 8 + 2 * c;
        int p0 = perm16(colj), p1 = perm16(colj + 1);
        y[rb0 + p0] = __uint_as_float(f2tf32(oc[dt][0] * inv0));
        y[rb0 + p1] = __uint_as_float(f2tf32(oc[dt][1] * inv0));
        y[rb1 + p0] = __uint_as_float(f2tf32(oc[dt][2] * inv1));
        y[rb1 + p1] = __uint_as_float(f2tf32(oc[dt][3] * inv1));
    }
}

// ---------------------------------------------------------------------------
extern "C" void kernel_launch(void* const* d_in, const int* in_sizes, int n_in,
                              void* d_out, int out_size)
{
    const float* x      = (const float*)d_in[0];
    const float* W_attn = (const float*)d_in[1];
    const float* b_attn = (const float*)d_in[2];
    const float* W_proj = (const float*)d_in[3];
    const float* b_proj = (const float*)d_in[4];
    float* out = (float*)d_out;

    float *xc, *wta, *wpt, *qkv, *vt, *y;
    cudaGetSymbolAddress((void**)&xc,  g_xc);
    cudaGetSymbolAddress((void**)&wta, g_wta);
    cudaGetSymbolAddress((void**)&wpt, g_wpt);
    cudaGetSymbolAddress((void**)&qkv, g_qkv);
    cudaGetSymbolAddress((void**)&vt,  g_vt);
    cudaGetSymbolAddress((void**)&y,   g_y);

    cudaFuncSetAttribute(gemm_tf32<0>, cudaFuncAttributeMaxDynamicSharedMemorySize, GEMM_SMEM);
    cudaFuncSetAttribute(gemm_tf32<1>, cudaFuncAttributeMaxDynamicSharedMemorySize, GEMM_SMEM);
    cudaFuncSetAttribute(flash_attn_tf32, cudaFuncAttributeMaxDynamicSharedMemorySize, FA_SMEM);

    // Prepass: convert/permute x; transpose+convert weights
    const int n4 = M_ROWS * C_EMBD / 4;
    cvt_perm_kernel<<<(n4 + 255) / 256, 256>>>(x, xc, n4, C_EMBD / 4);
    tr_cvt_perm_kernel<<<dim3(3 * C_EMBD / 32, C_EMBD / 32), dim3(32, 8)>>>(W_attn, wta, C_EMBD, 3 * C_EMBD);
    tr_cvt_perm_kernel<<<dim3(C_EMBD / 32, C_EMBD / 32), dim3(32, 8)>>>(W_proj, wpt, C_EMBD, C_EMBD);

    // QKV projection (writes q/k permuted tf32 + Vt)
    gemm_tf32<1><<<dim3(3 * C_EMBD / 128, M_ROWS / 128), 256, GEMM_SMEM>>>(
        xc, wta, b_attn, qkv, vt, M_ROWS, 3 * C_EMBD, C_EMBD);

    // Flash attention
    flash_attn_tf32<<<dim3(T_SEQ / 128, BATCH * NH), 256, FA_SMEM>>>(qkv, vt, y);

    // Output projection (plain fp32 out)
    gemm_tf32<0><<<dim3(C_EMBD / 128, M_ROWS / 128), 256, GEMM_SMEM>>>(
        y, wpt, b_proj, out, nullptr, M_ROWS, C_EMBD, C_EMBD);
}

// round 7
// speedup vs baseline: 3.4542x; 1.8317x over previous
#include <cuda_runtime.h>
#include <cuda_fp16.h>
#include <math.h>

#define C_EMBD 768
#define NH     12
#define HD     64
#define T_SEQ  4096
#define BATCH  2
#define M_ROWS (BATCH * T_SEQ)   // 8192

// Scratch (no cudaMalloc allowed)
__device__ __half g_xc [(size_t)M_ROWS * C_EMBD];          // x fp16 [M][K]
__device__ __half g_wta[(size_t)3 * C_EMBD * C_EMBD];      // W_attn^T fp16 [N][K]
__device__ __half g_wpt[(size_t)C_EMBD * C_EMBD];          // W_proj^T fp16 [N][K]
__device__ __half g_qkv[(size_t)M_ROWS * 3 * C_EMBD];      // q(pre-scaled),k fp16; v unused
__device__ __half g_vt [(size_t)BATCH * NH * HD * T_SEQ];  // V^T fp16 [b][h][d][T]
__device__ __half g_y  [(size_t)M_ROWS * C_EMBD];          // attn out fp16 [M][C]

#define QSCALE (0.125f * 1.4426950408889634f)  // 1/sqrt(64) * log2(e)

__device__ __forceinline__ float ex2(float x) {
    float r;
    asm("ex2.approx.f32 %0, %1;" : "=f"(r) : "f"(x));
    return r;
}
__device__ __forceinline__ unsigned pack_h2(float lo, float hi) {
    unsigned r;
    asm("cvt.rn.f16x2.f32 %0, %1, %2;" : "=r"(r) : "f"(hi), "f"(lo));
    return r;
}
// D += A(16x16) * B(16x8), fp16 in, fp32 accum
__device__ __forceinline__ void mma16816(float* c, const unsigned* a,
                                         unsigned b0, unsigned b1) {
    asm volatile(
        "mma.sync.aligned.m16n8k16.row.col.f32.f16.f16.f32 "
        "{%0,%1,%2,%3}, {%4,%5,%6,%7}, {%8,%9}, {%0,%1,%2,%3};\n"
        : "+f"(c[0]), "+f"(c[1]), "+f"(c[2]), "+f"(c[3])
        : "r"(a[0]), "r"(a[1]), "r"(a[2]), "r"(a[3]), "r"(b0), "r"(b1));
}
__device__ __forceinline__ void ldsm4(unsigned* r, unsigned addr) {
    asm volatile("ldmatrix.sync.aligned.m8n8.x4.shared.b16 {%0,%1,%2,%3}, [%4];"
        : "=r"(r[0]), "=r"(r[1]), "=r"(r[2]), "=r"(r[3]) : "r"(addr));
}
__device__ __forceinline__ unsigned smem_u32(const void* p) {
    return (unsigned)__cvta_generic_to_shared(p);
}
__device__ __forceinline__ void cp_async16(unsigned saddr, const void* g) {
    asm volatile("cp.async.cg.shared.global [%0], [%1], 16;\n" :: "r"(saddr), "l"(g));
}
#define CP_COMMIT() asm volatile("cp.async.commit_group;\n")
#define CP_WAIT(n)  asm volatile("cp.async.wait_group %0;\n" :: "n"(n))

// ---------------------------------------------------------------------------
// Prepass 1: fp32 -> fp16 elementwise.
// ---------------------------------------------------------------------------
__global__ void cvt_h_kernel(const float* __restrict__ in, __half* __restrict__ out, int n4)
{
    int idx = blockIdx.x * blockDim.x + threadIdx.x;
    if (idx >= n4) return;
    float4 v = ((const float4*)in)[idx];
    ((unsigned*)out)[idx * 2]     = pack_h2(v.x, v.y);
    ((unsigned*)out)[idx * 2 + 1] = pack_h2(v.z, v.w);
}

// ---------------------------------------------------------------------------
// Prepass 2: W[K][N] -> Wt[N][K] fp16 transpose. 32x32 smem tiles.
// ---------------------------------------------------------------------------
__global__ void tr_h_kernel(const float* __restrict__ W, __half* __restrict__ Wt,
                            int K, int N)
{
    __shared__ float tile[32][33];
    int k0 = blockIdx.y * 32, n0 = blockIdx.x * 32;
    int tx = threadIdx.x, ty = threadIdx.y;
    #pragma unroll
    for (int r = 0; r < 4; r++)
        tile[ty + 8 * r][tx] = W[(size_t)(k0 + ty + 8 * r) * N + n0 + tx];
    __syncthreads();
    #pragma unroll
    for (int r = 0; r < 4; r++) {
        int n = ty + 8 * r;
        Wt[(size_t)(n0 + n) * K + k0 + tx] = __float2half_rn(tile[tx][n]);
    }
}

// ---------------------------------------------------------------------------
// FP16 GEMM + bias: C[M][N] = A[M][K] @ Wt[N][K]^T + bias.
// 128x128 tile, BK=32, 256 thr = 8 warps (4M x 2N), warp 32x64.
// ldmatrix fragments, m16n8k16 mma. MODE 0: fp32 out. MODE 1: qkv epilogue.
// ---------------------------------------------------------------------------
#define ASTRh 40   // halves; 80B rows -> conflict-free ldmatrix
#define GEMM_SMEM (2 * 2 * 128 * ASTRh * 2)  // 2 tensors x 2 stages x 128x40 halves

template<int MODE>
__global__ __launch_bounds__(256, 2) void gemm_h(
    const __half* __restrict__ A, const __half* __restrict__ B,
    const float* __restrict__ bias, float* __restrict__ Cf,
    __half* __restrict__ Ch, __half* __restrict__ Vt, int M, int N, int K)
{
    extern __shared__ __half smh[];
    __half* As = smh;                    // 2 x [128][ASTRh]
    __half* Bs = smh + 2 * 128 * ASTRh;  // 2 x [128][ASTRh]

    const int tid  = threadIdx.x;
    const int warp = tid >> 5, lane = tid & 31;
    const int wm = warp & 3, wn = warp >> 2;
    const int g = lane >> 2, c = lane & 3;

    // ldmatrix per-lane row/col offsets
    const int arow = (lane & 7) + ((lane >> 3) & 1) * 8;
    const int acol = (lane >> 4) * 8;
    const int brow = (lane & 7) + (lane >> 4) * 8;
    const int bcol = ((lane >> 3) & 1) * 8;

    const int by = blockIdx.y, bx = blockIdx.x;
    const __half* Ab = A + (size_t)by * 128 * K;
    const __half* Bb = B + (size_t)bx * 128 * K;

    float acc[2][8][4];
    #pragma unroll
    for (int mt = 0; mt < 2; mt++)
        #pragma unroll
        for (int nt = 0; nt < 8; nt++)
            #pragma unroll
            for (int r = 0; r < 4; r++) acc[mt][nt][r] = 0.f;

    // stage loads: 512 chunks (16B = 8 halves) each for A and B; 2 per thread
    #define LOAD_STAGE(s, k0)                                                   \
        {                                                                       \
            _Pragma("unroll")                                                   \
            for (int i = 0; i < 2; i++) {                                       \
                int cid = tid + i * 256;                                        \
                int row = cid >> 2, ch = (cid & 3) * 8;                         \
                cp_async16(smem_u32(&As[(s) * 128 * ASTRh + row * ASTRh + ch]), \
                           &Ab[(size_t)row * K + (k0) + ch]);                   \
                cp_async16(smem_u32(&Bs[(s) * 128 * ASTRh + row * ASTRh + ch]), \
                           &Bb[(size_t)row * K + (k0) + ch]);                   \
            }                                                                   \
        }

    LOAD_STAGE(0, 0);
    CP_COMMIT();

    const unsigned AsU = smem_u32(As), BsU = smem_u32(Bs);
    const int NK = K / 32;
    for (int kt = 0; kt < NK; kt++) {
        __syncthreads();
        if (kt + 1 < NK) LOAD_STAGE((kt + 1) & 1, (kt + 1) * 32);
        CP_COMMIT();
        CP_WAIT(1);
        __syncthreads();

        const unsigned Au = AsU + (kt & 1) * 128 * ASTRh * 2;
        const unsigned Bu = BsU + (kt & 1) * 128 * ASTRh * 2;

        #pragma unroll
        for (int ks = 0; ks < 2; ks++) {
            const int kk = ks * 16;
            unsigned a[2][4];
            #pragma unroll
            for (int mt = 0; mt < 2; mt++)
                ldsm4(a[mt], Au + (((wm * 32 + mt * 16 + arow) * ASTRh + kk + acol) << 1));
            #pragma unroll
            for (int np = 0; np < 4; np++) {
                unsigned b[4];
                ldsm4(b, Bu + (((wn * 64 + np * 16 + brow) * ASTRh + kk + bcol) << 1));
                mma16816(acc[0][2 * np],     a[0], b[0], b[1]);
                mma16816(acc[1][2 * np],     a[1], b[0], b[1]);
                mma16816(acc[0][2 * np + 1], a[0], b[2], b[3]);
                mma16816(acc[1][2 * np + 1], a[1], b[2], b[3]);
            }
        }
    }

    #pragma unroll
    for (int mt = 0; mt < 2; mt++) {
        #pragma unroll
        for (int nt = 0; nt < 8; nt++) {
            int row0 = by * 128 + wm * 32 + mt * 16 + g;
            int col  = bx * 128 + wn * 64 + nt * 8 + 2 * c;
            float2 bv = *(const float2*)&bias[col];
            float v00 = acc[mt][nt][0] + bv.x, v01 = acc[mt][nt][1] + bv.y;
            float v10 = acc[mt][nt][2] + bv.x, v11 = acc[mt][nt][3] + bv.y;
            if (MODE == 0) {
                *(float2*)&Cf[(size_t)row0 * N + col]       = make_float2(v00, v01);
                *(float2*)&Cf[(size_t)(row0 + 8) * N + col] = make_float2(v10, v11);
            } else {
                if (col < C_EMBD) { // q: fold softmax scale (incl log2e)
                    v00 *= QSCALE; v01 *= QSCALE; v10 *= QSCALE; v11 *= QSCALE;
                }
                if (col < 2 * C_EMBD) {   // q, k regions: fp16 pairs
                    *(unsigned*)&Ch[(size_t)row0 * N + col]       = pack_h2(v00, v01);
                    *(unsigned*)&Ch[(size_t)(row0 + 8) * N + col] = pack_h2(v10, v11);
                } else {                  // v: transpose into Vt[b][h][d][T]
                    int cv = col - 2 * C_EMBD;
                    int hh = cv >> 6, d = cv & 63;
                    int bb = row0 >> 12, tt = row0 & 4095;
                    size_t base = ((size_t)(bb * NH + hh) * HD + d) * T_SEQ;
                    Vt[base + tt]             = __float2half_rn(v00);
                    Vt[base + T_SEQ + tt]     = __float2half_rn(v01);
                    Vt[base + tt + 8]         = __float2half_rn(v10);
                    Vt[base + T_SEQ + tt + 8] = __float2half_rn(v11);
                }
            }
        }
    }
}

// ---------------------------------------------------------------------------
// Flash attention, fp16 mma. Br=128, Bc=64, 256 thr = 8 warps (16 rows each).
// K double-buffered; V single-buffered awaited post-softmax (R6 pipeline).
// Q pre-scaled fp16; ldmatrix fragments everywhere; P round-trips smem fp16.
// ---------------------------------------------------------------------------
#define KSTRh 72   // halves; 144B rows -> conflict-free ldmatrix
#define FA_SMEM ((2 * 64 * KSTRh + 64 * KSTRh + 128 * KSTRh) * 2)

__global__ __launch_bounds__(256, 2) void flash_attn_h(
    const __half* __restrict__ qkv, const __half* __restrict__ vt,
    __half* __restrict__ y)
{
    extern __shared__ __half smh[];
    __half* sK  = smh;                    // 2 x [64][KSTRh] (rows=key, cols=d)
    __half* sV  = sK + 2 * 64 * KSTRh;    // [64][KSTRh]     (rows=d, cols=key)
    __half* sPQ = sV + 64 * KSTRh;        // [128][KSTRh]    (Q staging, then P)

    const int tid  = threadIdx.x;
    const int warp = tid >> 5, lane = tid & 31;
    const int g = lane >> 2, c = lane & 3;
    const int arow = (lane & 7) + ((lane >> 3) & 1) * 8;
    const int acol = (lane >> 4) * 8;
    const int brow = (lane & 7) + (lane >> 4) * 8;
    const int bcol = ((lane >> 3) & 1) * 8;

    const int qb = blockIdx.x;
    const int bh = blockIdx.y;
    const int b = bh / NH, h = bh % NH;

    const __half* qp  = qkv + (size_t)(b * T_SEQ + qb * 128) * (3 * C_EMBD) + h * HD;
    const __half* kp  = qkv + (size_t)b * T_SEQ * (3 * C_EMBD) + C_EMBD + h * HD;
    const __half* vtp = vt + (size_t)(b * NH + h) * HD * T_SEQ;

    #define LOAD_K(s, t0)                                                       \
        {                                                                       \
            _Pragma("unroll")                                                   \
            for (int i = 0; i < 2; i++) {                                       \
                int cid = tid + i * 256;                                        \
                int row = cid >> 3, ch = (cid & 7) * 8;                         \
                cp_async16(smem_u32(&sK[(s) * 64 * KSTRh + row * KSTRh + ch]),  \
                           &kp[(size_t)((t0) + row) * (3 * C_EMBD) + ch]);      \
            }                                                                   \
        }
    #define LOAD_V(t0)                                                          \
        {                                                                       \
            _Pragma("unroll")                                                   \
            for (int i = 0; i < 2; i++) {                                       \
                int cid = tid + i * 256;                                        \
                int row = cid >> 3, ch = (cid & 7) * 8;                         \
                cp_async16(smem_u32(&sV[row * KSTRh + ch]),                     \
                           &vtp[(size_t)row * T_SEQ + (t0) + ch]);              \
            }                                                                   \
        }

    // ---- stage Q (fp16, pre-scaled) ----
    #pragma unroll
    for (int i = 0; i < 4; i++) {
        int cid = tid + i * 256;
        int row = cid >> 3, ch = (cid & 7) * 8;
        cp_async16(smem_u32(&sPQ[row * KSTRh + ch]),
                   &qp[(size_t)row * (3 * C_EMBD) + ch]);
    }
    CP_COMMIT();
    LOAD_K(0, 0);
    CP_COMMIT();
    CP_WAIT(1);          // Q arrived (K0 in flight)
    __syncthreads();

    const unsigned KsU = smem_u32(sK), VsU = smem_u32(sV), PqU = smem_u32(sPQ);

    // ---- Q fragments into registers ----
    const int r0 = 16 * warp + g;
    unsigned qa[4][4];
    #pragma unroll
    for (int ks = 0; ks < 4; ks++)
        ldsm4(qa[ks], PqU + (((warp * 16 + arow) * KSTRh + ks * 16 + acol) << 1));

    float m0r = -INFINITY, m1r = -INFINITY, l0 = 0.f, l1 = 0.f;
    float oc[8][4];
    #pragma unroll
    for (int dt = 0; dt < 8; dt++)
        #pragma unroll
        for (int r = 0; r < 4; r++) oc[dt][r] = 0.f;

    const int NT = T_SEQ / 64;
    for (int t = 0; t < NT; t++) {
        __syncthreads();                    // prior-iter smem reads done
        LOAD_V(t * 64);
        CP_COMMIT();                        // group: V(t)
        if (t + 1 < NT) LOAD_K((t + 1) & 1, (t + 1) * 64);
        CP_COMMIT();                        // group: K(t+1) (possibly empty)
        CP_WAIT(2);                         // K(t) arrived
        __syncthreads();

        const unsigned Ku = KsU + (t & 1) * 64 * KSTRh * 2;

        // ---- S = Q @ K^T ----
        float sc[8][4];
        #pragma unroll
        for (int nt = 0; nt < 8; nt++)
            #pragma unroll
            for (int r = 0; r < 4; r++) sc[nt][r] = 0.f;

        #pragma unroll
        for (int ks = 0; ks < 4; ks++) {
            #pragma unroll
            for (int np = 0; np < 4; np++) {
                unsigned kb[4];
                ldsm4(kb, Ku + (((np * 16 + brow) * KSTRh + ks * 16 + bcol) << 1));
                mma16816(sc[2 * np],     qa[ks], kb[0], kb[1]);
                mma16816(sc[2 * np + 1], qa[ks], kb[2], kb[3]);
            }
        }

        // ---- online softmax (base-2; scale folded into Q) ----
        float rm0 = -INFINITY, rm1 = -INFINITY;
        #pragma unroll
        for (int nt = 0; nt < 8; nt++) {
            rm0 = fmaxf(rm0, fmaxf(sc[nt][0], sc[nt][1]));
            rm1 = fmaxf(rm1, fmaxf(sc[nt][2], sc[nt][3]));
        }
        rm0 = fmaxf(rm0, __shfl_xor_sync(0xffffffffu, rm0, 1));
        rm0 = fmaxf(rm0, __shfl_xor_sync(0xffffffffu, rm0, 2));
        rm1 = fmaxf(rm1, __shfl_xor_sync(0xffffffffu, rm1, 1));
        rm1 = fmaxf(rm1, __shfl_xor_sync(0xffffffffu, rm1, 2));

        float mn0 = fmaxf(m0r, rm0), mn1 = fmaxf(m1r, rm1);
        float corr0 = ex2(m0r - mn0), corr1 = ex2(m1r - mn1);
        m0r = mn0; m1r = mn1;

        float s0 = 0.f, s1 = 0.f;
        #pragma unroll
        for (int nt = 0; nt < 8; nt++) {
            float p0 = ex2(sc[nt][0] - mn0); sc[nt][0] = p0; s0 += p0;
            float p1 = ex2(sc[nt][1] - mn0); sc[nt][1] = p1; s0 += p1;
            float p2 = ex2(sc[nt][2] - mn1); sc[nt][2] = p2; s1 += p2;
            float p3 = ex2(sc[nt][3] - mn1); sc[nt][3] = p3; s1 += p3;
        }
        s0 += __shfl_xor_sync(0xffffffffu, s0, 1);
        s0 += __shfl_xor_sync(0xffffffffu, s0, 2);
        s1 += __shfl_xor_sync(0xffffffffu, s1, 1);
        s1 += __shfl_xor_sync(0xffffffffu, s1, 2);
        l0 = l0 * corr0 + s0;
        l1 = l1 * corr1 + s1;

        #pragma unroll
        for (int dt = 0; dt < 8; dt++) {
            oc[dt][0] *= corr0; oc[dt][1] *= corr0;
            oc[dt][2] *= corr1; oc[dt][3] *= corr1;
        }

        // ---- write P (fp16 pairs) — warp-private rows ----
        #pragma unroll
        for (int nt = 0; nt < 8; nt++) {
            int col = nt * 8 + 2 * c;
            *(unsigned*)&sPQ[(r0    ) * KSTRh + col] = pack_h2(sc[nt][0], sc[nt][1]);
            *(unsigned*)&sPQ[(r0 + 8) * KSTRh + col] = pack_h2(sc[nt][2], sc[nt][3]);
        }
        __syncwarp();

        CP_WAIT(1);          // V(t) arrived (K(t+1) may still be in flight)
        __syncthreads();

        // ---- O += P @ V ----
        #pragma unroll
        for (int ks = 0; ks < 4; ks++) {
            unsigned pa[4];
            ldsm4(pa, PqU + (((warp * 16 + arow) * KSTRh + ks * 16 + acol) << 1));
            #pragma unroll
            for (int np = 0; np < 4; np++) {
                unsigned vb[4];
                ldsm4(vb, VsU + (((np * 16 + brow) * KSTRh + ks * 16 + bcol) << 1));
                mma16816(oc[2 * np],     pa, vb[0], vb[1]);
                mma16816(oc[2 * np + 1], pa, vb[2], vb[3]);
            }
        }
    }

    // ---- epilogue: normalize, write y fp16 ----
    const float inv0 = 1.f / l0, inv1 = 1.f / l1;
    const int t_0 = qb * 128 + r0;
    const size_t rb0 = (size_t)(b * T_SEQ + t_0) * C_EMBD;
    const size_t rb1 = (size_t)(b * T_SEQ + t_0 + 8) * C_EMBD;
    #pragma unroll
    for (int dt = 0; dt < 8; dt++) {
        int col = h * HD + dt * 8 + 2 * c;
        *(unsigned*)&y[rb0 + col] = pack_h2(oc[dt][0] * inv0, oc[dt][1] * inv0);
        *(unsigned*)&y[rb1 + col] = pack_h2(oc[dt][2] * inv1, oc[dt][3] * inv1);
    }
}

// ---------------------------------------------------------------------------
extern "C" void kernel_launch(void* const* d_in, const int* in_sizes, int n_in,
                              void* d_out, int out_size)
{
    const float* x      = (const float*)d_in[0];
    const float* W_attn = (const float*)d_in[1];
    const float* b_attn = (const float*)d_in[2];
    const float* W_proj = (const float*)d_in[3];
    const float* b_proj = (const float*)d_in[4];
    float* out = (float*)d_out;

    __half *xc, *wta, *wpt, *qkv, *vt, *y;
    cudaGetSymbolAddress((void**)&xc,  g_xc);
    cudaGetSymbolAddress((void**)&wta, g_wta);
    cudaGetSymbolAddress((void**)&wpt, g_wpt);
    cudaGetSymbolAddress((void**)&qkv, g_qkv);
    cudaGetSymbolAddress((void**)&vt,  g_vt);
    cudaGetSymbolAddress((void**)&y,   g_y);

    cudaFuncSetAttribute(gemm_h<0>, cudaFuncAttributeMaxDynamicSharedMemorySize, GEMM_SMEM);
    cudaFuncSetAttribute(gemm_h<1>, cudaFuncAttributeMaxDynamicSharedMemorySize, GEMM_SMEM);
    cudaFuncSetAttribute(flash_attn_h, cudaFuncAttributeMaxDynamicSharedMemorySize, FA_SMEM);

    // Prepass: fp32 -> fp16 (x), transpose+fp16 (weights)
    const int n4 = M_ROWS * C_EMBD / 4;
    cvt_h_kernel<<<(n4 + 255) / 256, 256>>>(x, xc, n4);
    tr_h_kernel<<<dim3(3 * C_EMBD / 32, C_EMBD / 32), dim3(32, 8)>>>(W_attn, wta, C_EMBD, 3 * C_EMBD);
    tr_h_kernel<<<dim3(C_EMBD / 32, C_EMBD / 32), dim3(32, 8)>>>(W_proj, wpt, C_EMBD, C_EMBD);

    // QKV projection (writes q pre-scaled / k fp16 + Vt)
    gemm_h<1><<<dim3(3 * C_EMBD / 128, M_ROWS / 128), 256, GEMM_SMEM>>>(
        xc, wta, b_attn, nullptr, qkv, vt, M_ROWS, 3 * C_EMBD, C_EMBD);

    // Flash attention (fp16 mma)
    flash_attn_h<<<dim3(T_SEQ / 128, BATCH * NH), 256, FA_SMEM>>>(qkv, vt, y);

    // Output projection (fp32 out + bias)
    gemm_h<0><<<dim3(C_EMBD / 128, M_ROWS / 128), 256, GEMM_SMEM>>>(
        y, wpt, b_proj, out, nullptr, nullptr, M_ROWS, C_EMBD, C_EMBD);
}

// round 8
// speedup vs baseline: 3.8660x; 1.1192x over previous
#include <cuda_runtime.h>
#include <cuda_fp16.h>
#include <math.h>

#define C_EMBD 768
#define NH     12
#define HD     64
#define T_SEQ  4096
#define BATCH  2
#define M_ROWS (BATCH * T_SEQ)   // 8192

// Scratch (no cudaMalloc allowed)
__device__ __half g_xc [(size_t)M_ROWS * C_EMBD];          // x fp16 [M][K]
__device__ __half g_wta[(size_t)3 * C_EMBD * C_EMBD];      // W_attn^T fp16 [N][K]
__device__ __half g_wpt[(size_t)C_EMBD * C_EMBD];          // W_proj^T fp16 [N][K]
__device__ __half g_qkv[(size_t)M_ROWS * 3 * C_EMBD];      // q(pre-scaled),k fp16
__device__ __half g_vt [(size_t)BATCH * NH * HD * T_SEQ];  // V^T fp16 [b][h][d][T]
__device__ __half g_y  [(size_t)M_ROWS * C_EMBD];          // attn out fp16 [M][C]

#define QSCALE (0.125f * 1.4426950408889634f)  // 1/sqrt(64) * log2(e)

__device__ __forceinline__ float ex2(float x) {
    float r;
    asm("ex2.approx.f32 %0, %1;" : "=f"(r) : "f"(x));
    return r;
}
__device__ __forceinline__ unsigned pack_h2(float lo, float hi) {
    unsigned r;
    asm("cvt.rn.f16x2.f32 %0, %1, %2;" : "=r"(r) : "f"(hi), "f"(lo));
    return r;
}
__device__ __forceinline__ void mma16816(float* c, const unsigned* a,
                                         unsigned b0, unsigned b1) {
    asm volatile(
        "mma.sync.aligned.m16n8k16.row.col.f32.f16.f16.f32 "
        "{%0,%1,%2,%3}, {%4,%5,%6,%7}, {%8,%9}, {%0,%1,%2,%3};\n"
        : "+f"(c[0]), "+f"(c[1]), "+f"(c[2]), "+f"(c[3])
        : "r"(a[0]), "r"(a[1]), "r"(a[2]), "r"(a[3]), "r"(b0), "r"(b1));
}
__device__ __forceinline__ void ldsm4(unsigned* r, unsigned addr) {
    asm volatile("ldmatrix.sync.aligned.m8n8.x4.shared.b16 {%0,%1,%2,%3}, [%4];"
        : "=r"(r[0]), "=r"(r[1]), "=r"(r[2]), "=r"(r[3]) : "r"(addr));
}
__device__ __forceinline__ unsigned smem_u32(const void* p) {
    return (unsigned)__cvta_generic_to_shared(p);
}
__device__ __forceinline__ void cp_async16(unsigned saddr, const void* g) {
    asm volatile("cp.async.cg.shared.global [%0], [%1], 16;\n" :: "r"(saddr), "l"(g));
}
#define CP_COMMIT() asm volatile("cp.async.commit_group;\n")
#define CP_WAIT(n)  asm volatile("cp.async.wait_group %0;\n" :: "n"(n))

// ---------------------------------------------------------------------------
// Prepass 1: fp32 -> fp16 elementwise.
// ---------------------------------------------------------------------------
__global__ void cvt_h_kernel(const float* __restrict__ in, __half* __restrict__ out, int n4)
{
    int idx = blockIdx.x * blockDim.x + threadIdx.x;
    if (idx >= n4) return;
    float4 v = ((const float4*)in)[idx];
    ((unsigned*)out)[idx * 2]     = pack_h2(v.x, v.y);
    ((unsigned*)out)[idx * 2 + 1] = pack_h2(v.z, v.w);
}

// ---------------------------------------------------------------------------
// Prepass 2: W[K][N] -> Wt[N][K] fp16 transpose. 32x32 smem tiles.
// ---------------------------------------------------------------------------
__global__ void tr_h_kernel(const float* __restrict__ W, __half* __restrict__ Wt,
                            int K, int N)
{
    __shared__ float tile[32][33];
    int k0 = blockIdx.y * 32, n0 = blockIdx.x * 32;
    int tx = threadIdx.x, ty = threadIdx.y;
    #pragma unroll
    for (int r = 0; r < 4; r++)
        tile[ty + 8 * r][tx] = W[(size_t)(k0 + ty + 8 * r) * N + n0 + tx];
    __syncthreads();
    #pragma unroll
    for (int r = 0; r < 4; r++) {
        int n = ty + 8 * r;
        Wt[(size_t)(n0 + n) * K + k0 + tx] = __float2half_rn(tile[tx][n]);
    }
}

// ---------------------------------------------------------------------------
// FP16 GEMM + bias: 128x128 tile, BK=32, 3-stage cp.async, 1 sync/iter.
// 256 thr = 8 warps (4M x 2N). MODE 0: fp32 out. MODE 1: qkv epilogue.
// ---------------------------------------------------------------------------
#define ASTRh 40   // halves; 80B rows -> conflict-free ldmatrix
#define GEMM_SMEM (2 * 3 * 128 * ASTRh * 2)

template<int MODE>
__global__ __launch_bounds__(256, 2) void gemm_h(
    const __half* __restrict__ A, const __half* __restrict__ B,
    const float* __restrict__ bias, float* __restrict__ Cf,
    __half* __restrict__ Ch, __half* __restrict__ Vt, int M, int N, int K)
{
    extern __shared__ __half smh[];
    __half* As = smh;                    // 3 x [128][ASTRh]
    __half* Bs = smh + 3 * 128 * ASTRh;  // 3 x [128][ASTRh]

    const int tid  = threadIdx.x;
    const int warp = tid >> 5, lane = tid & 31;
    const int wm = warp & 3, wn = warp >> 2;
    const int g = lane >> 2, c = lane & 3;

    const int arow = (lane & 7) + ((lane >> 3) & 1) * 8;
    const int acol = (lane >> 4) * 8;
    const int brow = (lane & 7) + (lane >> 4) * 8;
    const int bcol = ((lane >> 3) & 1) * 8;

    const int by = blockIdx.y, bx = blockIdx.x;
    const __half* Ab = A + (size_t)by * 128 * K;
    const __half* Bb = B + (size_t)bx * 128 * K;

    float acc[2][8][4];
    #pragma unroll
    for (int mt = 0; mt < 2; mt++)
        #pragma unroll
        for (int nt = 0; nt < 8; nt++)
            #pragma unroll
            for (int r = 0; r < 4; r++) acc[mt][nt][r] = 0.f;

    #define LOAD_STAGE(s, k0)                                                   \
        {                                                                       \
            _Pragma("unroll")                                                   \
            for (int i = 0; i < 2; i++) {                                       \
                int cid = tid + i * 256;                                        \
                int row = cid >> 2, ch = (cid & 3) * 8;                         \
                cp_async16(smem_u32(&As[(s) * 128 * ASTRh + row * ASTRh + ch]), \
                           &Ab[(size_t)row * K + (k0) + ch]);                   \
                cp_async16(smem_u32(&Bs[(s) * 128 * ASTRh + row * ASTRh + ch]), \
                           &Bb[(size_t)row * K + (k0) + ch]);                   \
            }                                                                   \
        }

    LOAD_STAGE(0, 0);  CP_COMMIT();
    LOAD_STAGE(1, 32); CP_COMMIT();

    const unsigned AsU = smem_u32(As), BsU = smem_u32(Bs);
    const int NK = K / 32;
    int cbuf = 0, lbuf = 2;
    for (int kt = 0; kt < NK; kt++) {
        CP_WAIT(1);          // stage kt arrived (kt+1 may be in flight)
        __syncthreads();
        if (kt + 2 < NK) LOAD_STAGE(lbuf, (kt + 2) * 32);
        CP_COMMIT();
        lbuf = (lbuf == 2) ? 0 : lbuf + 1;

        const unsigned Au = AsU + cbuf * 128 * ASTRh * 2;
        const unsigned Bu = BsU + cbuf * 128 * ASTRh * 2;
        cbuf = (cbuf == 2) ? 0 : cbuf + 1;

        #pragma unroll
        for (int ks = 0; ks < 2; ks++) {
            const int kk = ks * 16;
            unsigned a[2][4];
            #pragma unroll
            for (int mt = 0; mt < 2; mt++)
                ldsm4(a[mt], Au + (((wm * 32 + mt * 16 + arow) * ASTRh + kk + acol) << 1));
            #pragma unroll
            for (int np = 0; np < 4; np++) {
                unsigned b[4];
                ldsm4(b, Bu + (((wn * 64 + np * 16 + brow) * ASTRh + kk + bcol) << 1));
                mma16816(acc[0][2 * np],     a[0], b[0], b[1]);
                mma16816(acc[1][2 * np],     a[1], b[0], b[1]);
                mma16816(acc[0][2 * np + 1], a[0], b[2], b[3]);
                mma16816(acc[1][2 * np + 1], a[1], b[2], b[3]);
            }
        }
    }

    #pragma unroll
    for (int mt = 0; mt < 2; mt++) {
        #pragma unroll
        for (int nt = 0; nt < 8; nt++) {
            int row0 = by * 128 + wm * 32 + mt * 16 + g;
            int col  = bx * 128 + wn * 64 + nt * 8 + 2 * c;
            float2 bv = *(const float2*)&bias[col];
            float v00 = acc[mt][nt][0] + bv.x, v01 = acc[mt][nt][1] + bv.y;
            float v10 = acc[mt][nt][2] + bv.x, v11 = acc[mt][nt][3] + bv.y;
            if (MODE == 0) {
                *(float2*)&Cf[(size_t)row0 * N + col]       = make_float2(v00, v01);
                *(float2*)&Cf[(size_t)(row0 + 8) * N + col] = make_float2(v10, v11);
            } else {
                if (col < C_EMBD) { // q: fold softmax scale (incl log2e)
                    v00 *= QSCALE; v01 *= QSCALE; v10 *= QSCALE; v11 *= QSCALE;
                }
                if (col < 2 * C_EMBD) {   // q, k regions: fp16 pairs
                    *(unsigned*)&Ch[(size_t)row0 * N + col]       = pack_h2(v00, v01);
                    *(unsigned*)&Ch[(size_t)(row0 + 8) * N + col] = pack_h2(v10, v11);
                } else {                  // v: transpose into Vt[b][h][d][T]
                    int cv = col - 2 * C_EMBD;
                    int hh = cv >> 6, d = cv & 63;
                    int bb = row0 >> 12, tt = row0 & 4095;
                    size_t base = ((size_t)(bb * NH + hh) * HD + d) * T_SEQ;
                    Vt[base + tt]             = __float2half_rn(v00);
                    Vt[base + T_SEQ + tt]     = __float2half_rn(v01);
                    Vt[base + tt + 8]         = __float2half_rn(v10);
                    Vt[base + T_SEQ + tt + 8] = __float2half_rn(v11);
                }
            }
        }
    }
}

// ---------------------------------------------------------------------------
// Flash attention, fp16 mma. Br=128, Bc=64, 256 thr = 8 warps (16 rows each).
// K+V in one commit group, 3-stage pipeline, ONE syncthreads per tile.
// P kept in registers (QK C-frag == PV A-frag layout). Q pre-scaled fp16.
// ---------------------------------------------------------------------------
#define KSTRh 72   // halves; 144B rows -> conflict-free ldmatrix
#define FA_SMEM ((3 * 64 * KSTRh + 3 * 64 * KSTRh + 128 * KSTRh) * 2)

__global__ __launch_bounds__(256, 2) void flash_attn_h(
    const __half* __restrict__ qkv, const __half* __restrict__ vt,
    __half* __restrict__ y)
{
    extern __shared__ __half smh[];
    __half* sK = smh;                    // 3 x [64][KSTRh] (rows=key, cols=d)
    __half* sV = sK + 3 * 64 * KSTRh;    // 3 x [64][KSTRh] (rows=d, cols=key)
    __half* sQ = sV + 3 * 64 * KSTRh;    // [128][KSTRh]    (Q staging)

    const int tid  = threadIdx.x;
    const int warp = tid >> 5, lane = tid & 31;
    const int g = lane >> 2, c = lane & 3;
    const int arow = (lane & 7) + ((lane >> 3) & 1) * 8;
    const int acol = (lane >> 4) * 8;
    const int brow = (lane & 7) + (lane >> 4) * 8;
    const int bcol = ((lane >> 3) & 1) * 8;

    const int qb = blockIdx.x;
    const int bh = blockIdx.y;
    const int b = bh / NH, h = bh % NH;

    const __half* qp  = qkv + (size_t)(b * T_SEQ + qb * 128) * (3 * C_EMBD) + h * HD;
    const __half* kp  = qkv + (size_t)b * T_SEQ * (3 * C_EMBD) + C_EMBD + h * HD;
    const __half* vtp = vt + (size_t)(b * NH + h) * HD * T_SEQ;

    #define LOAD_KV(s, t0)                                                      \
        {                                                                       \
            _Pragma("unroll")                                                   \
            for (int i = 0; i < 2; i++) {                                       \
                int cid = tid + i * 256;                                        \
                int row = cid >> 3, ch = (cid & 7) * 8;                         \
                cp_async16(smem_u32(&sK[(s) * 64 * KSTRh + row * KSTRh + ch]),  \
                           &kp[(size_t)((t0) + row) * (3 * C_EMBD) + ch]);      \
                cp_async16(smem_u32(&sV[(s) * 64 * KSTRh + row * KSTRh + ch]),  \
                           &vtp[(size_t)row * T_SEQ + (t0) + ch]);              \
            }                                                                   \
        }

    // ---- prologue: Q group, then KV(0), KV(1) ----
    #pragma unroll
    for (int i = 0; i < 4; i++) {
        int cid = tid + i * 256;
        int row = cid >> 3, ch = (cid & 7) * 8;
        cp_async16(smem_u32(&sQ[row * KSTRh + ch]),
                   &qp[(size_t)row * (3 * C_EMBD) + ch]);
    }
    CP_COMMIT();
    LOAD_KV(0, 0);  CP_COMMIT();
    LOAD_KV(1, 64); CP_COMMIT();
    CP_WAIT(2);          // Q arrived
    __syncthreads();

    const unsigned KsU = smem_u32(sK), VsU = smem_u32(sV), QU = smem_u32(sQ);

    unsigned qa[4][4];
    #pragma unroll
    for (int ks = 0; ks < 4; ks++)
        ldsm4(qa[ks], QU + (((warp * 16 + arow) * KSTRh + ks * 16 + acol) << 1));

    float m0r = -INFINITY, m1r = -INFINITY, l0 = 0.f, l1 = 0.f;
    float oc[8][4];
    #pragma unroll
    for (int dt = 0; dt < 8; dt++)
        #pragma unroll
        for (int r = 0; r < 4; r++) oc[dt][r] = 0.f;

    const int NT = T_SEQ / 64;
    int cbuf = 0, lbuf = 2;
    for (int t = 0; t < NT; t++) {
        CP_WAIT(1);          // KV(t) arrived (KV(t+1) may be in flight)
        __syncthreads();
        if (t + 2 < NT) LOAD_KV(lbuf, (t + 2) * 64);
        CP_COMMIT();
        lbuf = (lbuf == 2) ? 0 : lbuf + 1;

        const unsigned Ku = KsU + cbuf * 64 * KSTRh * 2;
        const unsigned Vu = VsU + cbuf * 64 * KSTRh * 2;
        cbuf = (cbuf == 2) ? 0 : cbuf + 1;

        // ---- S = Q @ K^T ----
        float sc[8][4];
        #pragma unroll
        for (int nt = 0; nt < 8; nt++)
            #pragma unroll
            for (int r = 0; r < 4; r++) sc[nt][r] = 0.f;

        #pragma unroll
        for (int ks = 0; ks < 4; ks++) {
            #pragma unroll
            for (int np = 0; np < 4; np++) {
                unsigned kb[4];
                ldsm4(kb, Ku + (((np * 16 + brow) * KSTRh + ks * 16 + bcol) << 1));
                mma16816(sc[2 * np],     qa[ks], kb[0], kb[1]);
                mma16816(sc[2 * np + 1], qa[ks], kb[2], kb[3]);
            }
        }

        // ---- online softmax (base-2; scale folded into Q) ----
        float rm0 = -INFINITY, rm1 = -INFINITY;
        #pragma unroll
        for (int nt = 0; nt < 8; nt++) {
            rm0 = fmaxf(rm0, fmaxf(sc[nt][0], sc[nt][1]));
            rm1 = fmaxf(rm1, fmaxf(sc[nt][2], sc[nt][3]));
        }
        rm0 = fmaxf(rm0, __shfl_xor_sync(0xffffffffu, rm0, 1));
        rm0 = fmaxf(rm0, __shfl_xor_sync(0xffffffffu, rm0, 2));
        rm1 = fmaxf(rm1, __shfl_xor_sync(0xffffffffu, rm1, 1));
        rm1 = fmaxf(rm1, __shfl_xor_sync(0xffffffffu, rm1, 2));

        float mn0 = fmaxf(m0r, rm0), mn1 = fmaxf(m1r, rm1);
        float corr0 = ex2(m0r - mn0), corr1 = ex2(m1r - mn1);
        m0r = mn0; m1r = mn1;

        float s0 = 0.f, s1 = 0.f;
        #pragma unroll
        for (int nt = 0; nt < 8; nt++) {
            float p0 = ex2(sc[nt][0] - mn0); sc[nt][0] = p0; s0 += p0;
            float p1 = ex2(sc[nt][1] - mn0); sc[nt][1] = p1; s0 += p1;
            float p2 = ex2(sc[nt][2] - mn1); sc[nt][2] = p2; s1 += p2;
            float p3 = ex2(sc[nt][3] - mn1); sc[nt][3] = p3; s1 += p3;
        }
        s0 += __shfl_xor_sync(0xffffffffu, s0, 1);
        s0 += __shfl_xor_sync(0xffffffffu, s0, 2);
        s1 += __shfl_xor_sync(0xffffffffu, s1, 1);
        s1 += __shfl_xor_sync(0xffffffffu, s1, 2);
        l0 = l0 * corr0 + s0;
        l1 = l1 * corr1 + s1;

        #pragma unroll
        for (int dt = 0; dt < 8; dt++) {
            oc[dt][0] *= corr0; oc[dt][1] *= corr0;
            oc[dt][2] *= corr1; oc[dt][3] *= corr1;
        }

        // ---- O += P @ V  (P fragments direct from registers) ----
        #pragma unroll
        for (int ks = 0; ks < 4; ks++) {
            unsigned pa[4];
            pa[0] = pack_h2(sc[2 * ks][0],     sc[2 * ks][1]);
            pa[1] = pack_h2(sc[2 * ks][2],     sc[2 * ks][3]);
            pa[2] = pack_h2(sc[2 * ks + 1][0], sc[2 * ks + 1][1]);
            pa[3] = pack_h2(sc[2 * ks + 1][2], sc[2 * ks + 1][3]);
            #pragma unroll
            for (int np = 0; np < 4; np++) {
                unsigned vb[4];
                ldsm4(vb, Vu + (((np * 16 + brow) * KSTRh + ks * 16 + bcol) << 1));
                mma16816(oc[2 * np],     pa, vb[0], vb[1]);
                mma16816(oc[2 * np + 1], pa, vb[2], vb[3]);
            }
        }
    }

    // ---- epilogue: normalize, write y fp16 ----
    const float inv0 = 1.f / l0, inv1 = 1.f / l1;
    const int t_0 = qb * 128 + 16 * warp + g;
    const size_t rb0 = (size_t)(b * T_SEQ + t_0) * C_EMBD;
    const size_t rb1 = (size_t)(b * T_SEQ + t_0 + 8) * C_EMBD;
    #pragma unroll
    for (int dt = 0; dt < 8; dt++) {
        int col = h * HD + dt * 8 + 2 * c;
        *(unsigned*)&y[rb0 + col] = pack_h2(oc[dt][0] * inv0, oc[dt][1] * inv0);
        *(unsigned*)&y[rb1 + col] = pack_h2(oc[dt][2] * inv1, oc[dt][3] * inv1);
    }
}

// ---------------------------------------------------------------------------
extern "C" void kernel_launch(void* const* d_in, const int* in_sizes, int n_in,
                              void* d_out, int out_size)
{
    const float* x      = (const float*)d_in[0];
    const float* W_attn = (const float*)d_in[1];
    const float* b_attn = (const float*)d_in[2];
    const float* W_proj = (const float*)d_in[3];
    const float* b_proj = (const float*)d_in[4];
    float* out = (float*)d_out;

    __half *xc, *wta, *wpt, *qkv, *vt, *y;
    cudaGetSymbolAddress((void**)&xc,  g_xc);
    cudaGetSymbolAddress((void**)&wta, g_wta);
    cudaGetSymbolAddress((void**)&wpt, g_wpt);
    cudaGetSymbolAddress((void**)&qkv, g_qkv);
    cudaGetSymbolAddress((void**)&vt,  g_vt);
    cudaGetSymbolAddress((void**)&y,   g_y);

    cudaFuncSetAttribute(gemm_h<0>, cudaFuncAttributeMaxDynamicSharedMemorySize, GEMM_SMEM);
    cudaFuncSetAttribute(gemm_h<1>, cudaFuncAttributeMaxDynamicSharedMemorySize, GEMM_SMEM);
    cudaFuncSetAttribute(flash_attn_h, cudaFuncAttributeMaxDynamicSharedMemorySize, FA_SMEM);

    // Prepass: fp32 -> fp16 (x), transpose+fp16 (weights)
    const int n4 = M_ROWS * C_EMBD / 4;
    cvt_h_kernel<<<(n4 + 255) / 256, 256>>>(x, xc, n4);
    tr_h_kernel<<<dim3(3 * C_EMBD / 32, C_EMBD / 32), dim3(32, 8)>>>(W_attn, wta, C_EMBD, 3 * C_EMBD);
    tr_h_kernel<<<dim3(C_EMBD / 32, C_EMBD / 32), dim3(32, 8)>>>(W_proj, wpt, C_EMBD, C_EMBD);

    // QKV projection (writes q pre-scaled / k fp16 + Vt)
    gemm_h<1><<<dim3(3 * C_EMBD / 128, M_ROWS / 128), 256, GEMM_SMEM>>>(
        xc, wta, b_attn, nullptr, qkv, vt, M_ROWS, 3 * C_EMBD, C_EMBD);

    // Flash attention (fp16 mma)
    flash_attn_h<<<dim3(T_SEQ / 128, BATCH * NH), 256, FA_SMEM>>>(qkv, vt, y);

    // Output projection (fp32 out + bias)
    gemm_h<0><<<dim3(C_EMBD / 128, M_ROWS / 128), 256, GEMM_SMEM>>>(
        y, wpt, b_proj, out, nullptr, nullptr, M_ROWS, C_EMBD, C_EMBD);
}